// round 3
// baseline (speedup 1.0000x reference)
#include <cuda_runtime.h>
#include <cstdint>

#define NN 100000
#define EE 1600000
#define DH 128

// ---------------- device scratch (no runtime allocation allowed) ----------------
__device__ float g_agg[NN * DH];        // 51.2 MB  aggregated (raw sums)
__device__ float g_h[NN * DH];          // 51.2 MB  hidden activations (h0 then h1 in-place)
__device__ int   g_cnt[NN];
__device__ int   g_cur[NN];
__device__ int   g_off[NN];
__device__ int   g_srcsorted[EE];       // 6.4 MB
__device__ int   g_bsum[256];
__device__ int   g_bsum2[256];
__device__ float g_WlT0[DH * DH];
__device__ float g_WrT0[DH * DH];
__device__ float g_WlT1[DH * DH];
__device__ float g_WrT1[DH * DH];
__device__ float g_WhT[DH * 64];

// ---------------- helpers ----------------
__device__ __forceinline__ float mishf(float v) {
    float sp = (v > 15.f) ? v : log1pf(__expf(v));
    return v * tanhf(sp);
}

// ---------------- edge preprocessing ----------------
__global__ void k_zero_counts() {
    int i = blockIdx.x * blockDim.x + threadIdx.x;
    if (i < NN) { g_cnt[i] = 0; g_cur[i] = 0; }
}

// edge_index is int32 on device (JAX x64 disabled): layout [2][E]
__global__ void k_hist(const int* __restrict__ edge) {
    int e = blockIdx.x * blockDim.x + threadIdx.x;
    if (e < EE) {
        int dst = edge[EE + e];
        atomicAdd(&g_cnt[dst], 1);
    }
}

// block-level Hillis-Steele scan, 512 per block
__global__ void k_scan1() {
    __shared__ int s[512];
    int t = threadIdx.x;
    int i = blockIdx.x * 512 + t;
    int v = (i < NN) ? g_cnt[i] : 0;
    s[t] = v;
    __syncthreads();
    #pragma unroll
    for (int off = 1; off < 512; off <<= 1) {
        int add = (t >= off) ? s[t - off] : 0;
        __syncthreads();
        s[t] += add;
        __syncthreads();
    }
    if (i < NN) g_off[i] = s[t] - v;           // exclusive within chunk
    if (t == 511) g_bsum[blockIdx.x] = s[511]; // chunk total
}

#define NB_SCAN ((NN + 511) / 512)   // 196

__global__ void k_scan2() {
    __shared__ int s[256];
    int t = threadIdx.x;
    int v = (t < NB_SCAN) ? g_bsum[t] : 0;
    s[t] = v;
    __syncthreads();
    #pragma unroll
    for (int off = 1; off < 256; off <<= 1) {
        int add = (t >= off) ? s[t - off] : 0;
        __syncthreads();
        s[t] += add;
        __syncthreads();
    }
    if (t < NB_SCAN) g_bsum2[t] = s[t] - v;    // exclusive block offsets
}

__global__ void k_scan3() {
    int i = blockIdx.x * blockDim.x + threadIdx.x;
    if (i < NN) g_off[i] += g_bsum2[i >> 9];
}

__global__ void k_scatter(const int* __restrict__ edge) {
    int e = blockIdx.x * blockDim.x + threadIdx.x;
    if (e < EE) {
        int src = edge[e];
        int dst = edge[EE + e];
        int pos = g_off[dst] + atomicAdd(&g_cur[dst], 1);
        g_srcsorted[pos] = src;
    }
}

// ---------------- segmented mean-sum aggregation: one warp per destination ----------------
__global__ __launch_bounds__(256) void k_aggregate(const float* __restrict__ feat,
                                                   float* __restrict__ outp) {
    int w = (blockIdx.x * blockDim.x + threadIdx.x) >> 5;
    if (w >= NN) return;
    int lane = threadIdx.x & 31;
    int start = g_off[w];
    int c = g_cnt[w];
    const float4* f4 = (const float4*)feat;
    float4 acc = make_float4(0.f, 0.f, 0.f, 0.f);
    int sNext = (c > 0) ? g_srcsorted[start] : 0;
    for (int e = 0; e < c; e++) {
        int s = sNext;
        if (e + 1 < c) sNext = g_srcsorted[start + e + 1];
        float4 v = __ldg(&f4[s * 32 + lane]);
        acc.x += v.x; acc.y += v.y; acc.z += v.z; acc.w += v.w;
    }
    ((float4*)outp)[w * 32 + lane] = acc;
}

// ---------------- weight transpose: in [J][K] row-major -> out [K][J] ----------------
__global__ void k_transpose(const float* __restrict__ in, float* __restrict__ out,
                            int J, int K) {
    __shared__ float t[32][33];
    int kb = blockIdx.x * 32, jb = blockIdx.y * 32;
    int tx = threadIdx.x, ty = threadIdx.y;  // 32 x 8
    #pragma unroll
    for (int i = 0; i < 32; i += 8)
        t[ty + i][tx] = in[(jb + ty + i) * K + (kb + tx)];
    __syncthreads();
    #pragma unroll
    for (int i = 0; i < 32; i += 8)
        out[(kb + ty + i) * J + (jb + tx)] = t[tx][ty + i];
}

// ---------------- fused layer GEMM: out = mish((agg/cnt)@Wl^T + b + X@Wr^T) ----------------
// BM=64 rows/block, 256 threads, thread tile 8 rows x 4 cols. Weights are k-major [k][j].
#define LAYER_SMEM_FLOATS (64*128 + 64*128 + 128*128 + 128*128 + 128)
#define LAYER_SMEM_BYTES  (LAYER_SMEM_FLOATS * 4)

__global__ __launch_bounds__(256, 1) void k_layer_gemm(
    const float* __restrict__ agg, const float* __restrict__ xin,
    const float* __restrict__ WlT, const float* __restrict__ WrT,
    const float* __restrict__ bias, const int* __restrict__ cnt,
    float* __restrict__ outp) {
    extern __shared__ float smem[];
    float* As = smem;                    // [64][128]
    float* Xs = As + 64 * 128;           // [64][128]
    float4* Wl4 = (float4*)(Xs + 64 * 128);   // [128][32] float4 (k-major)
    float4* Wr4 = Wl4 + 128 * 32;
    float* bs = (float*)(Wr4 + 128 * 32);

    int tx = threadIdx.x;
    int row0 = blockIdx.x * 64;

    // load weights (direct copy, already k-major)
    const float4* gWl = (const float4*)WlT;
    const float4* gWr = (const float4*)WrT;
    #pragma unroll
    for (int it = 0; it < 16; it++) {
        int v = tx + it * 256;   // 0..4095
        Wl4[v] = gWl[v];
        Wr4[v] = gWr[v];
    }
    if (tx < 128) bs[tx] = bias[tx];

    // load A (normalized agg) and X tiles
    const float4* gA = (const float4*)agg;
    const float4* gX = (const float4*)xin;
    #pragma unroll
    for (int it = 0; it < 8; it++) {
        int v = tx + it * 256;   // 0..2047
        int r = v >> 5;
        int kv = v & 31;
        int row = row0 + r;
        float4 a = make_float4(0.f, 0.f, 0.f, 0.f);
        float4 xx = make_float4(0.f, 0.f, 0.f, 0.f);
        if (row < NN) {
            float inv = 1.f / fmaxf((float)cnt[row], 1.f);
            a = gA[row * 32 + kv];
            a.x *= inv; a.y *= inv; a.z *= inv; a.w *= inv;
            xx = gX[row * 32 + kv];
        }
        ((float4*)&As[r * 128])[kv] = a;
        ((float4*)&Xs[r * 128])[kv] = xx;
    }
    __syncthreads();

    int jv = tx & 31;            // 32 float4 column groups
    int r0 = (tx >> 5) * 8;      // 8 row groups of 8 rows

    float acc[8][4];
    #pragma unroll
    for (int r = 0; r < 8; r++)
        #pragma unroll
        for (int c = 0; c < 4; c++) acc[r][c] = 0.f;

    #pragma unroll 4
    for (int kb = 0; kb < 32; kb++) {
        float4 a4[8], x4_[8];
        #pragma unroll
        for (int r = 0; r < 8; r++) {
            a4[r] = *(const float4*)&As[(r0 + r) * 128 + kb * 4];
            x4_[r] = *(const float4*)&Xs[(r0 + r) * 128 + kb * 4];
        }
        int koff = kb * 4;
#define KSTEP(COMP)                                              \
        {                                                        \
            float4 wl = Wl4[koff * 32 + jv];                     \
            float4 wr = Wr4[koff * 32 + jv];                     \
            _Pragma("unroll")                                    \
            for (int r = 0; r < 8; r++) {                        \
                float a = a4[r].COMP, xx = x4_[r].COMP;          \
                acc[r][0] += a * wl.x + xx * wr.x;               \
                acc[r][1] += a * wl.y + xx * wr.y;               \
                acc[r][2] += a * wl.z + xx * wr.z;               \
                acc[r][3] += a * wl.w + xx * wr.w;               \
            }                                                    \
            koff++;                                              \
        }
        KSTEP(x) KSTEP(y) KSTEP(z) KSTEP(w)
#undef KSTEP
    }

    int jbase = jv * 4;
    float b0 = bs[jbase + 0], b1 = bs[jbase + 1], b2 = bs[jbase + 2], b3 = bs[jbase + 3];
    #pragma unroll
    for (int r = 0; r < 8; r++) {
        int row = row0 + r0 + r;
        if (row < NN) {
            float4 o;
            o.x = mishf(acc[r][0] + b0);
            o.y = mishf(acc[r][1] + b1);
            o.z = mishf(acc[r][2] + b2);
            o.w = mishf(acc[r][3] + b3);
            ((float4*)&outp[row * 128])[jv] = o;
        }
    }
}

// ---------------- head GEMM: out = h @ Wh^T + b   [N,128]x[128,64] ----------------
#define HEAD_SMEM_FLOATS (64*128 + 128*64 + 64)
#define HEAD_SMEM_BYTES  (HEAD_SMEM_FLOATS * 4)

__global__ __launch_bounds__(256, 1) void k_head_gemm(
    const float* __restrict__ hin, const float* __restrict__ WhT,
    const float* __restrict__ bias, float* __restrict__ outp) {
    extern __shared__ float smem[];
    float* As = smem;                       // [64][128]
    float4* Wh4 = (float4*)(As + 64 * 128); // [128][16] float4
    float* bs = (float*)(Wh4 + 128 * 16);

    int tx = threadIdx.x;
    int row0 = blockIdx.x * 64;

    const float4* gW = (const float4*)WhT;
    #pragma unroll
    for (int it = 0; it < 8; it++) {
        int v = tx + it * 256;  // 0..2047
        Wh4[v] = gW[v];
    }
    if (tx < 64) bs[tx] = bias[tx];

    const float4* gA = (const float4*)hin;
    #pragma unroll
    for (int it = 0; it < 8; it++) {
        int v = tx + it * 256;
        int r = v >> 5;
        int kv = v & 31;
        int row = row0 + r;
        float4 a = make_float4(0.f, 0.f, 0.f, 0.f);
        if (row < NN) a = gA[row * 32 + kv];
        ((float4*)&As[r * 128])[kv] = a;
    }
    __syncthreads();

    int jv = tx & 15;           // 16 float4 col groups -> 64 cols
    int r0 = (tx >> 4) * 4;     // 16 row groups of 4 rows

    float acc[4][4];
    #pragma unroll
    for (int r = 0; r < 4; r++)
        #pragma unroll
        for (int c = 0; c < 4; c++) acc[r][c] = 0.f;

    #pragma unroll 4
    for (int kb = 0; kb < 32; kb++) {
        float4 a4[4];
        #pragma unroll
        for (int r = 0; r < 4; r++)
            a4[r] = *(const float4*)&As[(r0 + r) * 128 + kb * 4];
        int koff = kb * 4;
#define KSTEPH(COMP)                                             \
        {                                                        \
            float4 w = Wh4[koff * 16 + jv];                      \
            _Pragma("unroll")                                    \
            for (int r = 0; r < 4; r++) {                        \
                float a = a4[r].COMP;                            \
                acc[r][0] += a * w.x;                            \
                acc[r][1] += a * w.y;                            \
                acc[r][2] += a * w.z;                            \
                acc[r][3] += a * w.w;                            \
            }                                                    \
            koff++;                                              \
        }
        KSTEPH(x) KSTEPH(y) KSTEPH(z) KSTEPH(w)
#undef KSTEPH
    }

    int jbase = jv * 4;
    float b0 = bs[jbase + 0], b1 = bs[jbase + 1], b2 = bs[jbase + 2], b3 = bs[jbase + 3];
    #pragma unroll
    for (int r = 0; r < 4; r++) {
        int row = row0 + r0 + r;
        if (row < NN) {
            float4 o;
            o.x = acc[r][0] + b0;
            o.y = acc[r][1] + b1;
            o.z = acc[r][2] + b2;
            o.w = acc[r][3] + b3;
            ((float4*)&outp[row * 64])[jv] = o;
        }
    }
}

// ---------------- launch ----------------
extern "C" void kernel_launch(void* const* d_in, const int* in_sizes, int n_in,
                              void* d_out, int out_size) {
    (void)in_sizes; (void)n_in;
    const float* x      = (const float*)d_in[0];
    const int*   edge   = (const int*)d_in[1];     // int32 on device (JAX x64 off)
    const float* W_l0   = (const float*)d_in[2];
    const float* b_l0   = (const float*)d_in[3];
    const float* W_r0   = (const float*)d_in[4];
    const float* W_l1   = (const float*)d_in[5];
    const float* b_l1   = (const float*)d_in[6];
    const float* W_r1   = (const float*)d_in[7];
    const float* W_head = (const float*)d_in[8];
    const float* b_head = (const float*)d_in[9];
    float* out = (float*)d_out;
    (void)out_size;

    // opt-in to >48KB dynamic smem (idempotent; safe during capture)
    cudaFuncSetAttribute(k_layer_gemm, cudaFuncAttributeMaxDynamicSharedMemorySize,
                         LAYER_SMEM_BYTES);
    cudaFuncSetAttribute(k_head_gemm, cudaFuncAttributeMaxDynamicSharedMemorySize,
                         HEAD_SMEM_BYTES);

    // resolve device-global addresses for kernel args
    float *agg_p, *h_p;
    int *cnt_p;
    float *wlt0_p, *wrt0_p, *wlt1_p, *wrt1_p, *wht_p;
    cudaGetSymbolAddress((void**)&agg_p,  g_agg);
    cudaGetSymbolAddress((void**)&h_p,    g_h);
    cudaGetSymbolAddress((void**)&cnt_p,  g_cnt);
    cudaGetSymbolAddress((void**)&wlt0_p, g_WlT0);
    cudaGetSymbolAddress((void**)&wrt0_p, g_WrT0);
    cudaGetSymbolAddress((void**)&wlt1_p, g_WlT1);
    cudaGetSymbolAddress((void**)&wrt1_p, g_WrT1);
    cudaGetSymbolAddress((void**)&wht_p,  g_WhT);

    // --- edge preprocessing: counting sort by destination ---
    k_zero_counts<<<(NN + 255) / 256, 256>>>();
    k_hist<<<EE / 256, 256>>>(edge);
    k_scan1<<<NB_SCAN, 512>>>();
    k_scan2<<<1, 256>>>();
    k_scan3<<<(NN + 255) / 256, 256>>>();
    k_scatter<<<EE / 256, 256>>>(edge);

    // --- weight transposes (to k-major) ---
    dim3 tb(32, 8);
    k_transpose<<<dim3(4, 4), tb>>>(W_l0, wlt0_p, 128, 128);
    k_transpose<<<dim3(4, 4), tb>>>(W_r0, wrt0_p, 128, 128);
    k_transpose<<<dim3(4, 4), tb>>>(W_l1, wlt1_p, 128, 128);
    k_transpose<<<dim3(4, 4), tb>>>(W_r1, wrt1_p, 128, 128);
    k_transpose<<<dim3(4, 2), tb>>>(W_head, wht_p, 64, 128);

    int agg_grid = (NN * 32 + 255) / 256;       // one warp per node
    int gemm_grid = (NN + 63) / 64;

    // --- layer 0 ---
    k_aggregate<<<agg_grid, 256>>>(x, agg_p);
    k_layer_gemm<<<gemm_grid, 256, LAYER_SMEM_BYTES>>>(agg_p, x, wlt0_p, wrt0_p,
                                                       b_l0, cnt_p, h_p);
    // --- layer 1 ---
    k_aggregate<<<agg_grid, 256>>>(h_p, agg_p);
    k_layer_gemm<<<gemm_grid, 256, LAYER_SMEM_BYTES>>>(agg_p, h_p, wlt1_p, wrt1_p,
                                                       b_l1, cnt_p, h_p);
    // --- head ---
    k_head_gemm<<<gemm_grid, 256, HEAD_SMEM_BYTES>>>(h_p, wht_p, b_head, out);
}

// round 6
// speedup vs baseline: 1.6192x; 1.6192x over previous
#include <cuda_runtime.h>
#include <cuda_bf16.h>
#include <cstdint>

#define NN 100000
#define EE 1600000
#define DH 128
#define NTILES ((NN + 127) / 128)   // 782

// ---------------- device scratch ----------------
__device__ float g_agg[NN * DH];
__device__ float g_h[NN * DH];
__device__ int   g_cnt[NN];
__device__ int   g_cur[NN];
__device__ int   g_off[NN];
__device__ int   g_srcsorted[EE];
__device__ int   g_bsum[256];
__device__ int   g_bsum2[256];
// prepped weights, bf16 hi/lo, layout ((hl*4 + chunk)*128 + n)*72 + kk
__device__ __align__(16) uint16_t g_WB0[2 * 4 * 128 * 72];   // layer 0: 147456 B
__device__ __align__(16) uint16_t g_WB1[2 * 4 * 128 * 72];   // layer 1
// head: ((hl*2 + chunk)*64 + n)*72 + kk
__device__ __align__(16) uint16_t g_WBh[2 * 2 * 64 * 72];    // 36864 B

// ---------------- helpers ----------------
__device__ __forceinline__ void split2(float a, float b, uint32_t& h, uint32_t& l) {
    __nv_bfloat16 ha = __float2bfloat16_rn(a);
    __nv_bfloat16 hb = __float2bfloat16_rn(b);
    __nv_bfloat16 la = __float2bfloat16_rn(a - __bfloat162float(ha));
    __nv_bfloat16 lb = __float2bfloat16_rn(b - __bfloat162float(hb));
    h = (uint32_t)__bfloat16_as_ushort(ha) | ((uint32_t)__bfloat16_as_ushort(hb) << 16);
    l = (uint32_t)__bfloat16_as_ushort(la) | ((uint32_t)__bfloat16_as_ushort(lb) << 16);
}
// mish(x) = x * r/(r+2), r = t^2 + 2t, t = e^x
__device__ __forceinline__ float mish2(float v) {
    float t = __expf(fminf(v, 30.f));
    float r = t * t + 2.f * t;
    return v * (r / (r + 2.f));
}
__device__ __forceinline__ void mma_bf16(float* c, const uint32_t* a, const uint32_t* b) {
    asm volatile(
        "mma.sync.aligned.m16n8k16.row.col.f32.bf16.bf16.f32 "
        "{%0,%1,%2,%3}, {%4,%5,%6,%7}, {%8,%9}, {%0,%1,%2,%3};"
        : "+f"(c[0]), "+f"(c[1]), "+f"(c[2]), "+f"(c[3])
        : "r"(a[0]), "r"(a[1]), "r"(a[2]), "r"(a[3]), "r"(b[0]), "r"(b[1]));
}

// ---------------- edge preprocessing (unchanged, passing) ----------------
__global__ void k_zero_counts() {
    int i = blockIdx.x * blockDim.x + threadIdx.x;
    if (i < NN) { g_cnt[i] = 0; g_cur[i] = 0; }
}
__global__ void k_hist(const int* __restrict__ edge) {
    int e = blockIdx.x * blockDim.x + threadIdx.x;
    if (e < EE) atomicAdd(&g_cnt[edge[EE + e]], 1);
}
__global__ void k_scan1() {
    __shared__ int s[512];
    int t = threadIdx.x;
    int i = blockIdx.x * 512 + t;
    int v = (i < NN) ? g_cnt[i] : 0;
    s[t] = v;
    __syncthreads();
    #pragma unroll
    for (int off = 1; off < 512; off <<= 1) {
        int add = (t >= off) ? s[t - off] : 0;
        __syncthreads();
        s[t] += add;
        __syncthreads();
    }
    if (i < NN) g_off[i] = s[t] - v;
    if (t == 511) g_bsum[blockIdx.x] = s[511];
}
#define NB_SCAN ((NN + 511) / 512)
__global__ void k_scan2() {
    __shared__ int s[256];
    int t = threadIdx.x;
    int v = (t < NB_SCAN) ? g_bsum[t] : 0;
    s[t] = v;
    __syncthreads();
    #pragma unroll
    for (int off = 1; off < 256; off <<= 1) {
        int add = (t >= off) ? s[t - off] : 0;
        __syncthreads();
        s[t] += add;
        __syncthreads();
    }
    if (t < NB_SCAN) g_bsum2[t] = s[t] - v;
}
__global__ void k_scan3() {
    int i = blockIdx.x * blockDim.x + threadIdx.x;
    if (i < NN) g_off[i] += g_bsum2[i >> 9];
}
__global__ void k_scatter(const int* __restrict__ edge) {
    int e = blockIdx.x * blockDim.x + threadIdx.x;
    if (e < EE) {
        int src = edge[e];
        int dst = edge[EE + e];
        int pos = g_off[dst] + atomicAdd(&g_cur[dst], 1);
        g_srcsorted[pos] = src;
    }
}

// ---------------- aggregation: one warp per destination (unchanged) ----------------
__global__ __launch_bounds__(256) void k_aggregate(const float* __restrict__ feat,
                                                   float* __restrict__ outp) {
    int w = (blockIdx.x * blockDim.x + threadIdx.x) >> 5;
    if (w >= NN) return;
    int lane = threadIdx.x & 31;
    int start = g_off[w];
    int c = g_cnt[w];
    const float4* f4 = (const float4*)feat;
    float4 acc = make_float4(0.f, 0.f, 0.f, 0.f);
    int sNext = (c > 0) ? g_srcsorted[start] : 0;
    for (int e = 0; e < c; e++) {
        int s = sNext;
        if (e + 1 < c) sNext = g_srcsorted[start + e + 1];
        float4 v = __ldg(&f4[s * 32 + lane]);
        acc.x += v.x; acc.y += v.y; acc.z += v.z; acc.w += v.w;
    }
    ((float4*)outp)[w * 32 + lane] = acc;
}

// ---------------- weight prep: fp32 -> bf16 hi/lo in GEMM smem layout ----------------
// layer: B[n][kg] = (kg<128 ? Wl[n][kg] : Wr[n][kg-128]); chunk = kg>>6, kk = kg&63
__global__ void k_prep_layer(const float* __restrict__ Wl, const float* __restrict__ Wr,
                             uint16_t* __restrict__ outw) {
    int idx = blockIdx.x * blockDim.x + threadIdx.x;   // 0..8191 float4 groups
    if (idx >= 8192) return;
    int n = idx >> 6;
    int kg = (idx & 63) * 4;
    const float* Ws = (kg < 128) ? Wl : Wr;
    float4 v = *(const float4*)&Ws[n * 128 + (kg & 127)];
    uint32_t h01, h23, l01, l23;
    split2(v.x, v.y, h01, l01);
    split2(v.z, v.w, h23, l23);
    int c = kg >> 6, kk = kg & 63;
    *(uint2*)&outw[((0 * 4 + c) * 128 + n) * 72 + kk] = make_uint2(h01, h23);
    *(uint2*)&outw[((4 + c) * 128 + n) * 72 + kk]     = make_uint2(l01, l23);
}
// head: B[n][k] = Wh[n][k], n<64, k<128; chunk = k>>6
__global__ void k_prep_head(const float* __restrict__ Wh, uint16_t* __restrict__ outw) {
    int idx = blockIdx.x * blockDim.x + threadIdx.x;   // 0..2047 float4 groups
    if (idx >= 2048) return;
    int n = idx >> 5;
    int kg = (idx & 31) * 4;
    float4 v = *(const float4*)&Wh[n * 128 + kg];
    uint32_t h01, h23, l01, l23;
    split2(v.x, v.y, h01, l01);
    split2(v.z, v.w, h23, l23);
    int c = kg >> 6, kk = kg & 63;
    *(uint2*)&outw[((0 * 2 + c) * 64 + n) * 72 + kk] = make_uint2(h01, h23);
    *(uint2*)&outw[((2 + c) * 64 + n) * 72 + kk]     = make_uint2(l01, l23);
}

// ================= mma.sync fused SAGE layer =================
// out = mish( [agg/cnt | x] @ [Wl|Wr]^T + b ), tile M=128, N=128, K=256 (4x64)
// smem bytes: bias 512 | Ah 18432 | Al 18432 | W 147456  (total 184832)
#define L_SM_BIAS 0
#define L_SM_A    512
#define L_SM_W    (512 + 2 * 18432)
#define L_SMEM_BYTES (L_SM_W + 147456)

__global__ __launch_bounds__(256, 1) void k_layer_tc(
    const float* __restrict__ agg, const float* __restrict__ xin,
    const uint16_t* __restrict__ wprep, const float* __restrict__ bias,
    const int* __restrict__ cnt, float* __restrict__ outp) {
    extern __shared__ __align__(16) char smem[];
    int t = threadIdx.x;
    int wid = t >> 5, lane = t & 31;
    int g = lane >> 2, q = lane & 3;
    int wm = wid & 3, wn = wid >> 2;       // warp tile: rows wm*32.., cols wn*64..
    int row0 = blockIdx.x * 128;

    // weights: straight copy (prepped layout)
    {
        const uint4* src = (const uint4*)wprep;
        uint4* dst = (uint4*)(smem + L_SM_W);
        #pragma unroll
        for (int it = 0; it < 36; it++) dst[t + it * 256] = src[t + it * 256];
    }
    if (t < 128) ((float*)(smem + L_SM_BIAS))[t] = bias[t];

    float acc[2][8][4];
    #pragma unroll
    for (int mi = 0; mi < 2; mi++)
        #pragma unroll
        for (int ni = 0; ni < 8; ni++)
            #pragma unroll
            for (int r = 0; r < 4; r++) acc[mi][ni][r] = 0.f;

    char* Ah = smem + L_SM_A;
    char* Al = Ah + 18432;

    for (int c = 0; c < 4; c++) {
        // ---- stage A chunk: fp32 -> bf16 hi/lo, stride 72 ----
        {
            const float4* src4 = (c < 2) ? (const float4*)agg : (const float4*)xin;
            int cb16 = (c & 1) * 16;
            #pragma unroll
            for (int it = 0; it < 8; it++) {
                int v = t + it * 256;          // 0..2047
                int row = v >> 4;
                int f = v & 15;
                int gr = row0 + row;
                float4 a = make_float4(0.f, 0.f, 0.f, 0.f);
                if (gr < NN) {
                    a = src4[gr * 32 + cb16 + f];
                    if (c < 2) {
                        float inv = 1.f / fmaxf((float)cnt[gr], 1.f);
                        a.x *= inv; a.y *= inv; a.z *= inv; a.w *= inv;
                    }
                }
                uint32_t h01, h23, l01, l23;
                split2(a.x, a.y, h01, l01);
                split2(a.z, a.w, h23, l23);
                int boff = row * 144 + f * 8;
                *(uint2*)(Ah + boff) = make_uint2(h01, h23);
                *(uint2*)(Al + boff) = make_uint2(l01, l23);
            }
        }
        __syncthreads();

        const char* Bh = smem + L_SM_W + (size_t)(0 * 4 + c) * 128 * 144;
        const char* Bl = smem + L_SM_W + (size_t)(4 + c) * 128 * 144;

        #pragma unroll
        for (int ks = 0; ks < 4; ks++) {
            int k0 = ks * 16;
            int kb = (k0 + 2 * q) * 2;         // byte offset along k
            uint32_t ah[2][4], al[2][4];
            #pragma unroll
            for (int mi = 0; mi < 2; mi++) {
                int rb = (wm * 32 + mi * 16 + g) * 144 + kb;
                ah[mi][0] = *(const uint32_t*)(Ah + rb);
                ah[mi][1] = *(const uint32_t*)(Ah + rb + 8 * 144);
                ah[mi][2] = *(const uint32_t*)(Ah + rb + 16);
                ah[mi][3] = *(const uint32_t*)(Ah + rb + 8 * 144 + 16);
                al[mi][0] = *(const uint32_t*)(Al + rb);
                al[mi][1] = *(const uint32_t*)(Al + rb + 8 * 144);
                al[mi][2] = *(const uint32_t*)(Al + rb + 16);
                al[mi][3] = *(const uint32_t*)(Al + rb + 8 * 144 + 16);
            }
            #pragma unroll
            for (int ni = 0; ni < 8; ni++) {
                int nb = (wn * 64 + ni * 8 + g) * 144 + kb;
                uint32_t bh[2], bl[2];
                bh[0] = *(const uint32_t*)(Bh + nb);
                bh[1] = *(const uint32_t*)(Bh + nb + 16);
                bl[0] = *(const uint32_t*)(Bl + nb);
                bl[1] = *(const uint32_t*)(Bl + nb + 16);
                #pragma unroll
                for (int mi = 0; mi < 2; mi++) {
                    mma_bf16(acc[mi][ni], ah[mi], bh);
                    mma_bf16(acc[mi][ni], al[mi], bh);
                    mma_bf16(acc[mi][ni], ah[mi], bl);
                }
            }
        }
        __syncthreads();
    }

    // ---- epilogue: bias + mish, float2 stores ----
    const float* bsm = (const float*)(smem + L_SM_BIAS);
    #pragma unroll
    for (int mi = 0; mi < 2; mi++) {
        #pragma unroll
        for (int ni = 0; ni < 8; ni++) {
            int col = wn * 64 + ni * 8 + 2 * q;
            float b0 = bsm[col], b1 = bsm[col + 1];
            int rlo = row0 + wm * 32 + mi * 16 + g;
            int rhi = rlo + 8;
            if (rlo < NN) {
                float2 o = make_float2(mish2(acc[mi][ni][0] + b0),
                                       mish2(acc[mi][ni][1] + b1));
                *(float2*)&outp[rlo * 128 + col] = o;
            }
            if (rhi < NN) {
                float2 o = make_float2(mish2(acc[mi][ni][2] + b0),
                                       mish2(acc[mi][ni][3] + b1));
                *(float2*)&outp[rhi * 128 + col] = o;
            }
        }
    }
}

// ================= mma.sync head: out = h @ Wh^T + b  [N,128]x[128,64] =================
// smem: bias 512 | Ah 18432 | Al 18432 | W 36864  (total 74240)
#define H_SM_BIAS 0
#define H_SM_A    512
#define H_SM_W    (512 + 2 * 18432)
#define H_SMEM_BYTES (H_SM_W + 36864)

__global__ __launch_bounds__(256, 1) void k_head_tc(
    const float* __restrict__ hin, const uint16_t* __restrict__ wprep,
    const float* __restrict__ bias, float* __restrict__ outp) {
    extern __shared__ __align__(16) char smem[];
    int t = threadIdx.x;
    int wid = t >> 5, lane = t & 31;
    int g = lane >> 2, q = lane & 3;
    int row0 = blockIdx.x * 128;

    {
        const uint4* src = (const uint4*)wprep;
        uint4* dst = (uint4*)(smem + H_SM_W);
        #pragma unroll
        for (int it = 0; it < 9; it++) dst[t + it * 256] = src[t + it * 256];
    }
    if (t < 64) ((float*)(smem + H_SM_BIAS))[t] = bias[t];

    float acc[8][4];
    #pragma unroll
    for (int ni = 0; ni < 8; ni++)
        #pragma unroll
        for (int r = 0; r < 4; r++) acc[ni][r] = 0.f;

    char* Ah = smem + H_SM_A;
    char* Al = Ah + 18432;

    for (int c = 0; c < 2; c++) {
        {
            const float4* src4 = (const float4*)hin;
            int cb16 = c * 16;
            #pragma unroll
            for (int it = 0; it < 8; it++) {
                int v = t + it * 256;
                int row = v >> 4;
                int f = v & 15;
                int gr = row0 + row;
                float4 a = make_float4(0.f, 0.f, 0.f, 0.f);
                if (gr < NN) a = src4[gr * 32 + cb16 + f];
                uint32_t h01, h23, l01, l23;
                split2(a.x, a.y, h01, l01);
                split2(a.z, a.w, h23, l23);
                int boff = row * 144 + f * 8;
                *(uint2*)(Ah + boff) = make_uint2(h01, h23);
                *(uint2*)(Al + boff) = make_uint2(l01, l23);
            }
        }
        __syncthreads();

        const char* Bh = smem + H_SM_W + (size_t)(0 * 2 + c) * 64 * 144;
        const char* Bl = smem + H_SM_W + (size_t)(2 + c) * 64 * 144;

        #pragma unroll
        for (int ks = 0; ks < 4; ks++) {
            int k0 = ks * 16;
            int kb = (k0 + 2 * q) * 2;
            uint32_t ah[4], al[4];
            int rb = (wid * 16 + g) * 144 + kb;
            ah[0] = *(const uint32_t*)(Ah + rb);
            ah[1] = *(const uint32_t*)(Ah + rb + 8 * 144);
            ah[2] = *(const uint32_t*)(Ah + rb + 16);
            ah[3] = *(const uint32_t*)(Ah + rb + 8 * 144 + 16);
            al[0] = *(const uint32_t*)(Al + rb);
            al[1] = *(const uint32_t*)(Al + rb + 8 * 144);
            al[2] = *(const uint32_t*)(Al + rb + 16);
            al[3] = *(const uint32_t*)(Al + rb + 8 * 144 + 16);
            #pragma unroll
            for (int ni = 0; ni < 8; ni++) {
                int nb = (ni * 8 + g) * 144 + kb;
                uint32_t bh[2], bl[2];
                bh[0] = *(const uint32_t*)(Bh + nb);
                bh[1] = *(const uint32_t*)(Bh + nb + 16);
                bl[0] = *(const uint32_t*)(Bl + nb);
                bl[1] = *(const uint32_t*)(Bl + nb + 16);
                mma_bf16(acc[ni], ah, bh);
                mma_bf16(acc[ni], al, bh);
                mma_bf16(acc[ni], ah, bl);
            }
        }
        __syncthreads();
    }

    const float* bsm = (const float*)(smem + H_SM_BIAS);
    #pragma unroll
    for (int ni = 0; ni < 8; ni++) {
        int col = ni * 8 + 2 * q;
        float b0 = bsm[col], b1 = bsm[col + 1];
        int rlo = row0 + wid * 16 + g;
        int rhi = rlo + 8;
        if (rlo < NN)
            *(float2*)&outp[rlo * 64 + col] =
                make_float2(acc[ni][0] + b0, acc[ni][1] + b1);
        if (rhi < NN)
            *(float2*)&outp[rhi * 64 + col] =
                make_float2(acc[ni][2] + b0, acc[ni][3] + b1);
    }
}

// ---------------- launch ----------------
extern "C" void kernel_launch(void* const* d_in, const int* in_sizes, int n_in,
                              void* d_out, int out_size) {
    (void)in_sizes; (void)n_in; (void)out_size;
    const float* x      = (const float*)d_in[0];
    const int*   edge   = (const int*)d_in[1];     // int32 on device (JAX x64 off)
    const float* W_l0   = (const float*)d_in[2];
    const float* b_l0   = (const float*)d_in[3];
    const float* W_r0   = (const float*)d_in[4];
    const float* W_l1   = (const float*)d_in[5];
    const float* b_l1   = (const float*)d_in[6];
    const float* W_r1   = (const float*)d_in[7];
    const float* W_head = (const float*)d_in[8];
    const float* b_head = (const float*)d_in[9];
    float* out = (float*)d_out;

    cudaFuncSetAttribute(k_layer_tc, cudaFuncAttributeMaxDynamicSharedMemorySize,
                         L_SMEM_BYTES);
    cudaFuncSetAttribute(k_head_tc, cudaFuncAttributeMaxDynamicSharedMemorySize,
                         H_SMEM_BYTES);

    float *agg_p, *h_p;
    int *cnt_p;
    uint16_t *wb0_p, *wb1_p, *wbh_p;
    cudaGetSymbolAddress((void**)&agg_p, g_agg);
    cudaGetSymbolAddress((void**)&h_p,   g_h);
    cudaGetSymbolAddress((void**)&cnt_p, g_cnt);
    cudaGetSymbolAddress((void**)&wb0_p, g_WB0);
    cudaGetSymbolAddress((void**)&wb1_p, g_WB1);
    cudaGetSymbolAddress((void**)&wbh_p, g_WBh);

    // --- edge preprocessing: counting sort by destination ---
    k_zero_counts<<<(NN + 255) / 256, 256>>>();
    k_hist<<<EE / 256, 256>>>(edge);
    k_scan1<<<NB_SCAN, 512>>>();
    k_scan2<<<1, 256>>>();
    k_scan3<<<(NN + 255) / 256, 256>>>();
    k_scatter<<<EE / 256, 256>>>(edge);

    // --- weight prep (bf16 hi/lo) ---
    k_prep_layer<<<32, 256>>>(W_l0, W_r0, wb0_p);
    k_prep_layer<<<32, 256>>>(W_l1, W_r1, wb1_p);
    k_prep_head<<<8, 256>>>(W_head, wbh_p);

    int agg_grid = (NN * 32 + 255) / 256;

    // --- layer 0 ---
    k_aggregate<<<agg_grid, 256>>>(x, agg_p);
    k_layer_tc<<<NTILES, 256, L_SMEM_BYTES>>>(agg_p, x, wb0_p, b_l0, cnt_p, h_p);
    // --- layer 1 ---
    k_aggregate<<<agg_grid, 256>>>(h_p, agg_p);
    k_layer_tc<<<NTILES, 256, L_SMEM_BYTES>>>(agg_p, h_p, wb1_p, b_l1, cnt_p, h_p);
    // --- head ---
    k_head_tc<<<NTILES, 256, H_SMEM_BYTES>>>(h_p, wbh_p, b_head, out);
}

// round 8
// speedup vs baseline: 1.9713x; 1.2174x over previous
#include <cuda_runtime.h>
#include <cuda_bf16.h>
#include <cstdint>

#define NN 100000
#define EE 1600000
#define DH 128
#define NTILES ((NN + 127) / 128)   // 782
#define GRID_P 148

// ---------------- device scratch ----------------
__device__ __align__(16) uint16_t g_aggH[NN * DH];   // normalized agg, bf16 hi plane
__device__ __align__(16) uint16_t g_aggL[NN * DH];   // lo plane
__device__ __align__(16) uint16_t g_xH[NN * DH];     // GEMM x-input planes (h after layer)
__device__ __align__(16) uint16_t g_xL[NN * DH];
__device__ float g_h[NN * DH];                       // fp32 h (aggregation pass 2 input)
__device__ int   g_cnt[NN];
__device__ int   g_cur[NN];
__device__ int   g_off[NN];
__device__ int   g_srcsorted[EE];
__device__ int   g_bsum[256];
__device__ int   g_bsum2[256];
// prepped weights, bf16 hi/lo, layout ((hl*4 + chunk)*128 + n)*72 + kk
__device__ __align__(16) uint16_t g_WB0[2 * 4 * 128 * 72];
__device__ __align__(16) uint16_t g_WB1[2 * 4 * 128 * 72];
// head: ((hl*2 + chunk)*64 + n)*72 + kk
__device__ __align__(16) uint16_t g_WBh[2 * 2 * 64 * 72];

// ---------------- helpers ----------------
__device__ __forceinline__ void split2(float a, float b, uint32_t& h, uint32_t& l) {
    __nv_bfloat16 ha = __float2bfloat16_rn(a);
    __nv_bfloat16 hb = __float2bfloat16_rn(b);
    __nv_bfloat16 la = __float2bfloat16_rn(a - __bfloat162float(ha));
    __nv_bfloat16 lb = __float2bfloat16_rn(b - __bfloat162float(hb));
    h = (uint32_t)__bfloat16_as_ushort(ha) | ((uint32_t)__bfloat16_as_ushort(hb) << 16);
    l = (uint32_t)__bfloat16_as_ushort(la) | ((uint32_t)__bfloat16_as_ushort(lb) << 16);
}
__device__ __forceinline__ float mish2(float v) {
    float t = __expf(fminf(v, 30.f));
    float r = t * t + 2.f * t;
    return v * (r / (r + 2.f));
}
__device__ __forceinline__ void mma_bf16(float* c, const uint32_t* a, const uint32_t* b) {
    asm volatile(
        "mma.sync.aligned.m16n8k16.row.col.f32.bf16.bf16.f32 "
        "{%0,%1,%2,%3}, {%4,%5,%6,%7}, {%8,%9}, {%0,%1,%2,%3};"
        : "+f"(c[0]), "+f"(c[1]), "+f"(c[2]), "+f"(c[3])
        : "r"(a[0]), "r"(a[1]), "r"(a[2]), "r"(a[3]), "r"(b[0]), "r"(b[1]));
}

// ---------------- edge preprocessing (unchanged, passing) ----------------
__global__ void k_zero_counts() {
    int i = blockIdx.x * blockDim.x + threadIdx.x;
    if (i < NN) { g_cnt[i] = 0; g_cur[i] = 0; }
}
__global__ void k_hist(const int* __restrict__ edge) {
    int e = blockIdx.x * blockDim.x + threadIdx.x;
    if (e < EE) atomicAdd(&g_cnt[edge[EE + e]], 1);
}
__global__ void k_scan1() {
    __shared__ int s[512];
    int t = threadIdx.x;
    int i = blockIdx.x * 512 + t;
    int v = (i < NN) ? g_cnt[i] : 0;
    s[t] = v;
    __syncthreads();
    #pragma unroll
    for (int off = 1; off < 512; off <<= 1) {
        int add = (t >= off) ? s[t - off] : 0;
        __syncthreads();
        s[t] += add;
        __syncthreads();
    }
    if (i < NN) g_off[i] = s[t] - v;
    if (t == 511) g_bsum[blockIdx.x] = s[511];
}
#define NB_SCAN ((NN + 511) / 512)
__global__ void k_scan2() {
    __shared__ int s[256];
    int t = threadIdx.x;
    int v = (t < NB_SCAN) ? g_bsum[t] : 0;
    s[t] = v;
    __syncthreads();
    #pragma unroll
    for (int off = 1; off < 256; off <<= 1) {
        int add = (t >= off) ? s[t - off] : 0;
        __syncthreads();
        s[t] += add;
        __syncthreads();
    }
    if (t < NB_SCAN) g_bsum2[t] = s[t] - v;
}
__global__ void k_scan3() {
    int i = blockIdx.x * blockDim.x + threadIdx.x;
    if (i < NN) g_off[i] += g_bsum2[i >> 9];
}
__global__ void k_scatter(const int* __restrict__ edge) {
    int e = blockIdx.x * blockDim.x + threadIdx.x;
    if (e < EE) {
        int src = edge[e];
        int dst = edge[EE + e];
        int pos = g_off[dst] + atomicAdd(&g_cur[dst], 1);
        g_srcsorted[pos] = src;
    }
}

// ---------------- aggregation v2: shfl-batched indices, emits normalized bf16 planes ----
__global__ __launch_bounds__(256) void k_aggregate(const float* __restrict__ feat,
                                                   uint16_t* __restrict__ outH,
                                                   uint16_t* __restrict__ outL) {
    int w = (blockIdx.x * blockDim.x + threadIdx.x) >> 5;
    if (w >= NN) return;
    int lane = threadIdx.x & 31;
    int start = g_off[w];
    int c = g_cnt[w];
    const float4* f4 = (const float4*)feat;
    float4 acc = make_float4(0.f, 0.f, 0.f, 0.f);
    for (int base = 0; base < c; base += 32) {
        int idx = (base + lane < c) ? g_srcsorted[start + base + lane] : 0;
        int m = min(32, c - base);
        #pragma unroll 4
        for (int j = 0; j < m; j++) {
            int s = __shfl_sync(0xffffffffu, idx, j);
            float4 v = __ldg(&f4[s * 32 + lane]);
            acc.x += v.x; acc.y += v.y; acc.z += v.z; acc.w += v.w;
        }
    }
    float inv = 1.f / fmaxf((float)c, 1.f);
    acc.x *= inv; acc.y *= inv; acc.z *= inv; acc.w *= inv;
    uint32_t h01, h23, l01, l23;
    split2(acc.x, acc.y, h01, l01);
    split2(acc.z, acc.w, h23, l23);
    *(uint2*)&outH[w * 128 + lane * 4] = make_uint2(h01, h23);
    *(uint2*)&outL[w * 128 + lane * 4] = make_uint2(l01, l23);
}

// ---------------- weight prep: fp32 -> bf16 hi/lo in GEMM smem layout ----------------
__global__ void k_prep_layer(const float* __restrict__ Wl, const float* __restrict__ Wr,
                             uint16_t* __restrict__ outw) {
    int idx = blockIdx.x * blockDim.x + threadIdx.x;
    if (idx >= 8192) return;
    int n = idx >> 6;
    int kg = (idx & 63) * 4;
    const float* Ws = (kg < 128) ? Wl : Wr;
    float4 v = *(const float4*)&Ws[n * 128 + (kg & 127)];
    uint32_t h01, h23, l01, l23;
    split2(v.x, v.y, h01, l01);
    split2(v.z, v.w, h23, l23);
    int c = kg >> 6, kk = kg & 63;
    *(uint2*)&outw[((0 * 4 + c) * 128 + n) * 72 + kk] = make_uint2(h01, h23);
    *(uint2*)&outw[((4 + c) * 128 + n) * 72 + kk]     = make_uint2(l01, l23);
}
__global__ void k_prep_head(const float* __restrict__ Wh, uint16_t* __restrict__ outw) {
    int idx = blockIdx.x * blockDim.x + threadIdx.x;
    if (idx >= 2048) return;
    int n = idx >> 5;
    int kg = (idx & 31) * 4;
    float4 v = *(const float4*)&Wh[n * 128 + kg];
    uint32_t h01, h23, l01, l23;
    split2(v.x, v.y, h01, l01);
    split2(v.z, v.w, h23, l23);
    int c = kg >> 6, kk = kg & 63;
    *(uint2*)&outw[((0 * 2 + c) * 64 + n) * 72 + kk] = make_uint2(h01, h23);
    *(uint2*)&outw[((2 + c) * 64 + n) * 72 + kk]     = make_uint2(l01, l23);
}

// ---------------- staging primitives ----------------
struct StageRegs { uint4 rH[4], rL[4]; };

__device__ __forceinline__ void stage_load_planes(StageRegs& s, const uint16_t* pH,
                                                  const uint16_t* pL, int row0, int cb,
                                                  int t) {
    #pragma unroll
    for (int i = 0; i < 4; i++) {
        int v = t + i * 256, row = v >> 3, f = v & 7, gr = row0 + row;
        if (gr < NN) {
            s.rH[i] = *(const uint4*)(pH + gr * 128 + cb + f * 8);
            s.rL[i] = *(const uint4*)(pL + gr * 128 + cb + f * 8);
        } else {
            s.rH[i] = make_uint4(0, 0, 0, 0);
            s.rL[i] = make_uint4(0, 0, 0, 0);
        }
    }
}
__device__ __forceinline__ void stage_load_f32(StageRegs& s, const float* xf,
                                               int row0, int cb16, int t) {
    const float4* x4 = (const float4*)xf;
    #pragma unroll
    for (int i = 0; i < 4; i++) {
        int v = t + i * 256, row = v >> 3, f = v & 7, gr = row0 + row;
        float4 a = make_float4(0.f, 0.f, 0.f, 0.f);
        float4 b = make_float4(0.f, 0.f, 0.f, 0.f);
        if (gr < NN) {
            a = x4[gr * 32 + cb16 + f * 2];
            b = x4[gr * 32 + cb16 + f * 2 + 1];
        }
        uint32_t h01, h23, h45, h67, l01, l23, l45, l67;
        split2(a.x, a.y, h01, l01);
        split2(a.z, a.w, h23, l23);
        split2(b.x, b.y, h45, l45);
        split2(b.z, b.w, h67, l67);
        s.rH[i] = make_uint4(h01, h23, h45, h67);
        s.rL[i] = make_uint4(l01, l23, l45, l67);
    }
}
__device__ __forceinline__ void stage_store(const StageRegs& s, char* AH, char* AL, int t) {
    #pragma unroll
    for (int i = 0; i < 4; i++) {
        int v = t + i * 256, row = v >> 3, f = v & 7;
        *(uint4*)(AH + row * 144 + f * 16) = s.rH[i];
        *(uint4*)(AL + row * 144 + f * 16) = s.rL[i];
    }
}

// ================= persistent mma.sync fused SAGE layer =================
// out = mish( [agg_norm | x] @ [Wl|Wr]^T + b ), tiles of M=128, N=128, K=256 (4x64)
// smem: bias 512 | A double-buffer 2x(18432+18432) | W 147456  => 221696 B
#define L_SM_A    512
#define L_SM_W    (512 + 4 * 18432)
#define L_SMEM_BYTES (L_SM_W + 147456)

__global__ __launch_bounds__(256, 1) void k_layer_tc(
    const uint16_t* __restrict__ aggH, const uint16_t* __restrict__ aggL,
    const uint16_t* xH, const uint16_t* xL,          // planes path (no restrict: may alias out)
    const float* __restrict__ xf32,                  // fp32 path if non-null (layer 0)
    const uint16_t* __restrict__ wprep, const float* __restrict__ bias,
    float* __restrict__ hout, uint16_t* outH, uint16_t* outL, int write_f32) {
    extern __shared__ __align__(16) char smem[];
    int t = threadIdx.x;
    int wid = t >> 5, lane = t & 31;
    int g = lane >> 2, q = lane & 3;
    int wm = wid & 3, wn = wid >> 2;

    // weights + bias once per CTA
    {
        const uint4* src = (const uint4*)wprep;
        uint4* dst = (uint4*)(smem + L_SM_W);
        #pragma unroll
        for (int it = 0; it < 36; it++) dst[t + it * 256] = src[t + it * 256];
    }
    if (t < 128) ((float*)smem)[t] = bias[t];

    StageRegs sr;
    for (int tile = blockIdx.x; tile < NTILES; tile += GRID_P) {
        int row0 = tile * 128;

        float acc[2][8][4];
        #pragma unroll
        for (int mi = 0; mi < 2; mi++)
            #pragma unroll
            for (int ni = 0; ni < 8; ni++)
                #pragma unroll
                for (int r = 0; r < 4; r++) acc[mi][ni][r] = 0.f;

        // prologue: chunk 0 into buf 0
        stage_load_planes(sr, aggH, aggL, row0, 0, t);
        stage_store(sr, smem + L_SM_A, smem + L_SM_A + 18432, t);
        __syncthreads();

        #pragma unroll
        for (int c = 0; c < 4; c++) {
            // issue loads for next chunk before MMAs
            if (c < 3) {
                int nc = c + 1;
                if (nc < 2)
                    stage_load_planes(sr, aggH, aggL, row0, (nc & 1) * 64, t);
                else if (xf32)
                    stage_load_f32(sr, xf32, row0, (nc & 1) * 16, t);
                else
                    stage_load_planes(sr, xH, xL, row0, (nc & 1) * 64, t);
            }

            const char* Ah = smem + L_SM_A + (c & 1) * 36864;
            const char* Al = Ah + 18432;
            const char* Bh = smem + L_SM_W + (size_t)c * 18432;
            const char* Bl = smem + L_SM_W + (size_t)(4 + c) * 18432;

            #pragma unroll
            for (int ks = 0; ks < 4; ks++) {
                int kb = (ks * 16 + 2 * q) * 2;
                uint32_t ah[2][4], al[2][4];
                #pragma unroll
                for (int mi = 0; mi < 2; mi++) {
                    int rb = (wm * 32 + mi * 16 + g) * 144 + kb;
                    ah[mi][0] = *(const uint32_t*)(Ah + rb);
                    ah[mi][1] = *(const uint32_t*)(Ah + rb + 8 * 144);
                    ah[mi][2] = *(const uint32_t*)(Ah + rb + 16);
                    ah[mi][3] = *(const uint32_t*)(Ah + rb + 8 * 144 + 16);
                    al[mi][0] = *(const uint32_t*)(Al + rb);
                    al[mi][1] = *(const uint32_t*)(Al + rb + 8 * 144);
                    al[mi][2] = *(const uint32_t*)(Al + rb + 16);
                    al[mi][3] = *(const uint32_t*)(Al + rb + 8 * 144 + 16);
                }
                #pragma unroll
                for (int ni = 0; ni < 8; ni++) {
                    int nb = (wn * 64 + ni * 8 + g) * 144 + kb;
                    uint32_t bh[2], bl[2];
                    bh[0] = *(const uint32_t*)(Bh + nb);
                    bh[1] = *(const uint32_t*)(Bh + nb + 16);
                    bl[0] = *(const uint32_t*)(Bl + nb);
                    bl[1] = *(const uint32_t*)(Bl + nb + 16);
                    #pragma unroll
                    for (int mi = 0; mi < 2; mi++) {
                        mma_bf16(acc[mi][ni], ah[mi], bh);
                        mma_bf16(acc[mi][ni], al[mi], bh);
                        mma_bf16(acc[mi][ni], ah[mi], bl);
                    }
                }
            }

            if (c < 3) {
                char* AHn = smem + L_SM_A + ((c + 1) & 1) * 36864;
                stage_store(sr, AHn, AHn + 18432, t);
                __syncthreads();
            }
        }

        // epilogue: bias + mish -> fp32 h (optional) + bf16 hi/lo planes
        const float* bsm = (const float*)smem;
        #pragma unroll
        for (int mi = 0; mi < 2; mi++) {
            #pragma unroll
            for (int ni = 0; ni < 8; ni++) {
                int col = wn * 64 + ni * 8 + 2 * q;
                float b0 = bsm[col], b1 = bsm[col + 1];
                int rlo = row0 + wm * 32 + mi * 16 + g;
                int rhi = rlo + 8;
                if (rlo < NN) {
                    float o0 = mish2(acc[mi][ni][0] + b0);
                    float o1 = mish2(acc[mi][ni][1] + b1);
                    if (write_f32) *(float2*)&hout[rlo * 128 + col] = make_float2(o0, o1);
                    uint32_t hh, ll;
                    split2(o0, o1, hh, ll);
                    *(uint32_t*)&outH[rlo * 128 + col] = hh;
                    *(uint32_t*)&outL[rlo * 128 + col] = ll;
                }
                if (rhi < NN) {
                    float o0 = mish2(acc[mi][ni][2] + b0);
                    float o1 = mish2(acc[mi][ni][3] + b1);
                    if (write_f32) *(float2*)&hout[rhi * 128 + col] = make_float2(o0, o1);
                    uint32_t hh, ll;
                    split2(o0, o1, hh, ll);
                    *(uint32_t*)&outH[rhi * 128 + col] = hh;
                    *(uint32_t*)&outL[rhi * 128 + col] = ll;
                }
            }
        }
    }
}

// ================= persistent mma.sync head: out = h @ Wh^T + b =================
// smem: bias 512 | A double-buffer 4x18432 | W 36864 => 111104 B
#define H_SM_A    512
#define H_SM_W    (512 + 4 * 18432)
#define H_SMEM_BYTES (H_SM_W + 36864)

__global__ __launch_bounds__(256, 1) void k_head_tc(
    const uint16_t* __restrict__ xH, const uint16_t* __restrict__ xL,
    const uint16_t* __restrict__ wprep, const float* __restrict__ bias,
    float* __restrict__ outp) {
    extern __shared__ __align__(16) char smem[];
    int t = threadIdx.x;
    int wid = t >> 5, lane = t & 31;
    int g = lane >> 2, q = lane & 3;

    {
        const uint4* src = (const uint4*)wprep;
        uint4* dst = (uint4*)(smem + H_SM_W);
        #pragma unroll
        for (int it = 0; it < 9; it++) dst[t + it * 256] = src[t + it * 256];
    }
    if (t < 64) ((float*)smem)[t] = bias[t];

    StageRegs sr;
    for (int tile = blockIdx.x; tile < NTILES; tile += GRID_P) {
        int row0 = tile * 128;

        float acc[8][4];
        #pragma unroll
        for (int ni = 0; ni < 8; ni++)
            #pragma unroll
            for (int r = 0; r < 4; r++) acc[ni][r] = 0.f;

        stage_load_planes(sr, xH, xL, row0, 0, t);
        stage_store(sr, smem + H_SM_A, smem + H_SM_A + 18432, t);
        __syncthreads();

        #pragma unroll
        for (int c = 0; c < 2; c++) {
            if (c < 1) stage_load_planes(sr, xH, xL, row0, 64, t);

            const char* Ah = smem + H_SM_A + (c & 1) * 36864;
            const char* Al = Ah + 18432;
            const char* Bh = smem + H_SM_W + (size_t)c * 9216;
            const char* Bl = smem + H_SM_W + (size_t)(2 + c) * 9216;

            #pragma unroll
            for (int ks = 0; ks < 4; ks++) {
                int kb = (ks * 16 + 2 * q) * 2;
                uint32_t ah[4], al[4];
                int rb = (wid * 16 + g) * 144 + kb;
                ah[0] = *(const uint32_t*)(Ah + rb);
                ah[1] = *(const uint32_t*)(Ah + rb + 8 * 144);
                ah[2] = *(const uint32_t*)(Ah + rb + 16);
                ah[3] = *(const uint32_t*)(Ah + rb + 8 * 144 + 16);
                al[0] = *(const uint32_t*)(Al + rb);
                al[1] = *(const uint32_t*)(Al + rb + 8 * 144);
                al[2] = *(const uint32_t*)(Al + rb + 16);
                al[3] = *(const uint32_t*)(Al + rb + 8 * 144 + 16);
                #pragma unroll
                for (int ni = 0; ni < 8; ni++) {
                    int nb = (ni * 8 + g) * 144 + kb;
                    uint32_t bh[2], bl[2];
                    bh[0] = *(const uint32_t*)(Bh + nb);
                    bh[1] = *(const uint32_t*)(Bh + nb + 16);
                    bl[0] = *(const uint32_t*)(Bl + nb);
                    bl[1] = *(const uint32_t*)(Bl + nb + 16);
                    mma_bf16(acc[ni], ah, bh);
                    mma_bf16(acc[ni], al, bh);
                    mma_bf16(acc[ni], ah, bl);
                }
            }

            if (c < 1) {
                char* AHn = smem + H_SM_A + 36864;
                stage_store(sr, AHn, AHn + 18432, t);
                __syncthreads();
            }
        }

        const float* bsm = (const float*)smem;
        #pragma unroll
        for (int ni = 0; ni < 8; ni++) {
            int col = ni * 8 + 2 * q;
            float b0 = bsm[col], b1 = bsm[col + 1];
            int rlo = row0 + wid * 16 + g;
            int rhi = rlo + 8;
            if (rlo < NN)
                *(float2*)&outp[rlo * 64 + col] =
                    make_float2(acc[ni][0] + b0, acc[ni][1] + b1);
            if (rhi < NN)
                *(float2*)&outp[rhi * 64 + col] =
                    make_float2(acc[ni][2] + b0, acc[ni][3] + b1);
        }
        __syncthreads();   // protect buf0 before next tile's store
    }
}

// ---------------- launch ----------------
extern "C" void kernel_launch(void* const* d_in, const int* in_sizes, int n_in,
                              void* d_out, int out_size) {
    (void)in_sizes; (void)n_in; (void)out_size;
    const float* x      = (const float*)d_in[0];
    const int*   edge   = (const int*)d_in[1];     // int32 on device (JAX x64 off)
    const float* W_l0   = (const float*)d_in[2];
    const float* b_l0   = (const float*)d_in[3];
    const float* W_r0   = (const float*)d_in[4];
    const float* W_l1   = (const float*)d_in[5];
    const float* b_l1   = (const float*)d_in[6];
    const float* W_r1   = (const float*)d_in[7];
    const float* W_head = (const float*)d_in[8];
    const float* b_head = (const float*)d_in[9];
    float* out = (float*)d_out;

    cudaFuncSetAttribute(k_layer_tc, cudaFuncAttributeMaxDynamicSharedMemorySize,
                         L_SMEM_BYTES);
    cudaFuncSetAttribute(k_head_tc, cudaFuncAttributeMaxDynamicSharedMemorySize,
                         H_SMEM_BYTES);

    float *h_p;
    uint16_t *aggH_p, *aggL_p, *xH_p, *xL_p, *wb0_p, *wb1_p, *wbh_p;
    cudaGetSymbolAddress((void**)&h_p,    g_h);
    cudaGetSymbolAddress((void**)&aggH_p, g_aggH);
    cudaGetSymbolAddress((void**)&aggL_p, g_aggL);
    cudaGetSymbolAddress((void**)&xH_p,   g_xH);
    cudaGetSymbolAddress((void**)&xL_p,   g_xL);
    cudaGetSymbolAddress((void**)&wb0_p,  g_WB0);
    cudaGetSymbolAddress((void**)&wb1_p,  g_WB1);
    cudaGetSymbolAddress((void**)&wbh_p,  g_WBh);

    // --- edge preprocessing: counting sort by destination ---
    k_zero_counts<<<(NN + 255) / 256, 256>>>();
    k_hist<<<EE / 256, 256>>>(edge);
    k_scan1<<<NB_SCAN, 512>>>();
    k_scan2<<<1, 256>>>();
    k_scan3<<<(NN + 255) / 256, 256>>>();
    k_scatter<<<EE / 256, 256>>>(edge);

    // --- weight prep (bf16 hi/lo) ---
    k_prep_layer<<<32, 256>>>(W_l0, W_r0, wb0_p);
    k_prep_layer<<<32, 256>>>(W_l1, W_r1, wb1_p);
    k_prep_head<<<8, 256>>>(W_head, wbh_p);

    int agg_grid = (NN * 32 + 255) / 256;

    // --- layer 0: agg(x) -> planes; GEMM x from fp32; write h fp32 + planes ---
    k_aggregate<<<agg_grid, 256>>>(x, aggH_p, aggL_p);
    k_layer_tc<<<GRID_P, 256, L_SMEM_BYTES>>>(aggH_p, aggL_p, nullptr, nullptr, x,
                                              wb0_p, b_l0, h_p, xH_p, xL_p, 1);
    // --- layer 1: agg(h0 fp32) -> planes; GEMM x from h0 planes; write h1 planes ---
    k_aggregate<<<agg_grid, 256>>>(h_p, aggH_p, aggL_p);
    k_layer_tc<<<GRID_P, 256, L_SMEM_BYTES>>>(aggH_p, aggL_p, xH_p, xL_p, nullptr,
                                              wb1_p, b_l1, h_p, xH_p, xL_p, 0);
    // --- head: h1 planes ---
    k_head_tc<<<GRID_P, 256, H_SMEM_BYTES>>>(xH_p, xL_p, wbh_p, b_head, out);
}

// round 9
// speedup vs baseline: 2.0327x; 1.0312x over previous
#include <cuda_runtime.h>
#include <cuda_bf16.h>
#include <cstdint>

#define NN 100000
#define EE 1600000
#define DH 128
#define NTILES ((NN + 127) / 128)   // 782
#define GRID_P 148
#define NB_SCAN ((NN + 511) / 512)  // 196

// ---------------- device scratch ----------------
__device__ __align__(16) uint16_t g_aggH[NN * DH];
__device__ __align__(16) uint16_t g_aggL[NN * DH];
__device__ __align__(16) uint16_t g_xH[NN * DH];
__device__ __align__(16) uint16_t g_xL[NN * DH];
__device__ float g_h[NN * DH];
__device__ int   g_cnt[NN];
__device__ int   g_cur[NN];
__device__ int   g_off[NN];
__device__ int   g_srcsorted[EE];
__device__ unsigned long long g_pkt[NB_SCAN];   // decoupled-lookback packets
__device__ __align__(16) uint16_t g_WB0[2 * 4 * 128 * 72];
__device__ __align__(16) uint16_t g_WB1[2 * 4 * 128 * 72];
__device__ __align__(16) uint16_t g_WBh[2 * 2 * 64 * 72];

// ---------------- helpers ----------------
__device__ __forceinline__ void split2(float a, float b, uint32_t& h, uint32_t& l) {
    __nv_bfloat16 ha = __float2bfloat16_rn(a);
    __nv_bfloat16 hb = __float2bfloat16_rn(b);
    __nv_bfloat16 la = __float2bfloat16_rn(a - __bfloat162float(ha));
    __nv_bfloat16 lb = __float2bfloat16_rn(b - __bfloat162float(hb));
    h = (uint32_t)__bfloat16_as_ushort(ha) | ((uint32_t)__bfloat16_as_ushort(hb) << 16);
    l = (uint32_t)__bfloat16_as_ushort(la) | ((uint32_t)__bfloat16_as_ushort(lb) << 16);
}
__device__ __forceinline__ float mish2(float v) {
    float t = __expf(fminf(v, 30.f));
    float r = t * t + 2.f * t;
    return v * (r / (r + 2.f));
}
__device__ __forceinline__ void mma_bf16(float* c, const uint32_t* a, const uint32_t* b) {
    asm volatile(
        "mma.sync.aligned.m16n8k16.row.col.f32.bf16.bf16.f32 "
        "{%0,%1,%2,%3}, {%4,%5,%6,%7}, {%8,%9}, {%0,%1,%2,%3};"
        : "+f"(c[0]), "+f"(c[1]), "+f"(c[2]), "+f"(c[3])
        : "r"(a[0]), "r"(a[1]), "r"(a[2]), "r"(a[3]), "r"(b[0]), "r"(b[1]));
}

// ---------------- edge preprocessing ----------------
__global__ void k_zero_counts() {
    int i = blockIdx.x * blockDim.x + threadIdx.x;
    if (i < NN) { g_cnt[i] = 0; g_cur[i] = 0; }
    if (i < NB_SCAN) g_pkt[i] = 0ull;
}
__global__ void k_hist(const int* __restrict__ edge) {
    int e = blockIdx.x * blockDim.x + threadIdx.x;
    if (e < EE) atomicAdd(&g_cnt[edge[EE + e]], 1);
}
// single-pass decoupled-lookback exclusive scan of g_cnt -> g_off
__global__ void k_scan() {
    __shared__ int s[512];
    __shared__ int s_prefix;
    int t = threadIdx.x, b = blockIdx.x;
    int i = b * 512 + t;
    int v = (i < NN) ? g_cnt[i] : 0;
    s[t] = v;
    __syncthreads();
    #pragma unroll
    for (int off = 1; off < 512; off <<= 1) {
        int add = (t >= off) ? s[t - off] : 0;
        __syncthreads();
        s[t] += add;
        __syncthreads();
    }
    int total = s[511];
    if (t == 0) {
        atomicExch(&g_pkt[b], (1ull << 62) | (unsigned long long)total);
        long long prefix = 0;
        for (int j = b - 1; j >= 0; j--) {
            unsigned long long p;
            do { p = atomicAdd(&g_pkt[j], 0ull); } while ((p >> 62) == 0ull);
            prefix += (long long)(p & 0x3FFFFFFFFFFFFFFFull);
            if ((p >> 62) == 2ull) break;
        }
        atomicExch(&g_pkt[b], (2ull << 62) | (unsigned long long)(prefix + total));
        s_prefix = (int)prefix;
    }
    __syncthreads();
    if (i < NN) g_off[i] = s[t] - v + s_prefix;
}
__global__ void k_scatter(const int* __restrict__ edge) {
    int e = blockIdx.x * blockDim.x + threadIdx.x;
    if (e < EE) {
        int src = edge[e];
        int dst = edge[EE + e];
        int pos = g_off[dst] + atomicAdd(&g_cur[dst], 1);
        g_srcsorted[pos] = src;
    }
}

// ---------------- aggregation: shfl-batched, emits normalized bf16 planes ----------------
__global__ __launch_bounds__(256) void k_aggregate(const float* __restrict__ feat,
                                                   uint16_t* __restrict__ outH,
                                                   uint16_t* __restrict__ outL) {
    int w = (blockIdx.x * blockDim.x + threadIdx.x) >> 5;
    if (w >= NN) return;
    int lane = threadIdx.x & 31;
    int start = g_off[w];
    int c = g_cnt[w];
    const float4* f4 = (const float4*)feat;
    float4 acc = make_float4(0.f, 0.f, 0.f, 0.f);
    for (int base = 0; base < c; base += 32) {
        int idx = (base + lane < c) ? g_srcsorted[start + base + lane] : 0;
        int m = min(32, c - base);
        #pragma unroll 4
        for (int j = 0; j < m; j++) {
            int s = __shfl_sync(0xffffffffu, idx, j);
            float4 v = __ldg(&f4[s * 32 + lane]);
            acc.x += v.x; acc.y += v.y; acc.z += v.z; acc.w += v.w;
        }
    }
    float inv = 1.f / fmaxf((float)c, 1.f);
    acc.x *= inv; acc.y *= inv; acc.z *= inv; acc.w *= inv;
    uint32_t h01, h23, l01, l23;
    split2(acc.x, acc.y, h01, l01);
    split2(acc.z, acc.w, h23, l23);
    *(uint2*)&outH[w * 128 + lane * 4] = make_uint2(h01, h23);
    *(uint2*)&outL[w * 128 + lane * 4] = make_uint2(l01, l23);
}

// ---------------- fused weight prep (one launch) ----------------
__device__ __forceinline__ void prep_layer_elem(const float* Wl, const float* Wr,
                                                uint16_t* outw, int idx) {
    int n = idx >> 6;
    int kg = (idx & 63) * 4;
    const float* Ws = (kg < 128) ? Wl : Wr;
    float4 v = *(const float4*)&Ws[n * 128 + (kg & 127)];
    uint32_t h01, h23, l01, l23;
    split2(v.x, v.y, h01, l01);
    split2(v.z, v.w, h23, l23);
    int c = kg >> 6, kk = kg & 63;
    *(uint2*)&outw[((0 * 4 + c) * 128 + n) * 72 + kk] = make_uint2(h01, h23);
    *(uint2*)&outw[((4 + c) * 128 + n) * 72 + kk]     = make_uint2(l01, l23);
}
__global__ void k_prep_all(const float* __restrict__ Wl0, const float* __restrict__ Wr0,
                           const float* __restrict__ Wl1, const float* __restrict__ Wr1,
                           const float* __restrict__ Wh) {
    int b = blockIdx.x;
    int t = threadIdx.x;
    if (b < 32) {
        prep_layer_elem(Wl0, Wr0, g_WB0, b * 256 + t);
    } else if (b < 64) {
        prep_layer_elem(Wl1, Wr1, g_WB1, (b - 32) * 256 + t);
    } else {
        int idx = (b - 64) * 256 + t;     // 0..2047
        int n = idx >> 5;
        int kg = (idx & 31) * 4;
        float4 v = *(const float4*)&Wh[n * 128 + kg];
        uint32_t h01, h23, l01, l23;
        split2(v.x, v.y, h01, l01);
        split2(v.z, v.w, h23, l23);
        int c = kg >> 6, kk = kg & 63;
        *(uint2*)&g_WBh[((0 * 2 + c) * 64 + n) * 72 + kk] = make_uint2(h01, h23);
        *(uint2*)&g_WBh[((2 + c) * 64 + n) * 72 + kk]     = make_uint2(l01, l23);
    }
}

// ---------------- staging primitives ----------------
struct StageRegs { uint4 rH[4], rL[4]; };

__device__ __forceinline__ void stage_load_planes(StageRegs& s, const uint16_t* pH,
                                                  const uint16_t* pL, int row0, int cb,
                                                  int t) {
    #pragma unroll
    for (int i = 0; i < 4; i++) {
        int v = t + i * 256, row = v >> 3, f = v & 7, gr = row0 + row;
        if (gr < NN) {
            s.rH[i] = *(const uint4*)(pH + gr * 128 + cb + f * 8);
            s.rL[i] = *(const uint4*)(pL + gr * 128 + cb + f * 8);
        } else {
            s.rH[i] = make_uint4(0, 0, 0, 0);
            s.rL[i] = make_uint4(0, 0, 0, 0);
        }
    }
}
__device__ __forceinline__ void stage_load_f32(StageRegs& s, const float* xf,
                                               int row0, int cb16, int t) {
    const float4* x4 = (const float4*)xf;
    #pragma unroll
    for (int i = 0; i < 4; i++) {
        int v = t + i * 256, row = v >> 3, f = v & 7, gr = row0 + row;
        float4 a = make_float4(0.f, 0.f, 0.f, 0.f);
        float4 b = make_float4(0.f, 0.f, 0.f, 0.f);
        if (gr < NN) {
            a = x4[gr * 32 + cb16 + f * 2];
            b = x4[gr * 32 + cb16 + f * 2 + 1];
        }
        uint32_t h01, h23, h45, h67, l01, l23, l45, l67;
        split2(a.x, a.y, h01, l01);
        split2(a.z, a.w, h23, l23);
        split2(b.x, b.y, h45, l45);
        split2(b.z, b.w, h67, l67);
        s.rH[i] = make_uint4(h01, h23, h45, h67);
        s.rL[i] = make_uint4(l01, l23, l45, l67);
    }
}
__device__ __forceinline__ void stage_store(const StageRegs& s, char* AH, char* AL, int t) {
    #pragma unroll
    for (int i = 0; i < 4; i++) {
        int v = t + i * 256, row = v >> 3, f = v & 7;
        *(uint4*)(AH + row * 144 + f * 16) = s.rH[i];
        *(uint4*)(AL + row * 144 + f * 16) = s.rL[i];
    }
}

// ================= persistent pipelined mma.sync fused SAGE layer =================
// smem: bias 512 | A double-buffer 2x(18432+18432) | W 147456  => 221696 B
#define L_SM_A    512
#define L_SM_W    (512 + 4 * 18432)
#define L_SMEM_BYTES (L_SM_W + 147456)

__global__ __launch_bounds__(256, 1) void k_layer_tc(
    const uint16_t* __restrict__ aggH, const uint16_t* __restrict__ aggL,
    const uint16_t* xH, const uint16_t* xL,
    const float* __restrict__ xf32,
    const uint16_t* __restrict__ wprep, const float* __restrict__ bias,
    float* __restrict__ hout, uint16_t* outH, uint16_t* outL, int write_f32) {
    extern __shared__ __align__(16) char smem[];
    int t = threadIdx.x;
    int wid = t >> 5, lane = t & 31;
    int g = lane >> 2, q = lane & 3;
    int wm = wid & 3, wn = wid >> 2;

    {
        const uint4* src = (const uint4*)wprep;
        uint4* dst = (uint4*)(smem + L_SM_W);
        #pragma unroll
        for (int it = 0; it < 36; it++) dst[t + it * 256] = src[t + it * 256];
    }
    if (t < 128) ((float*)smem)[t] = bias[t];

    // chunk loader: cc in 0..3 (0,1 = agg planes; 2,3 = x)
    auto load_chunk = [&](StageRegs& s, int cc, int r0) {
        if (cc < 2)
            stage_load_planes(s, aggH, aggL, r0, cc * 64, t);
        else if (xf32)
            stage_load_f32(s, xf32, r0, (cc - 2) * 16, t);
        else
            stage_load_planes(s, xH, xL, r0, (cc - 2) * 64, t);
    };

    StageRegs sr;
    // prologue: first tile's chunk 0 into buf 0
    load_chunk(sr, 0, blockIdx.x * 128);
    stage_store(sr, smem + L_SM_A, smem + L_SM_A + 18432, t);
    __syncthreads();

    for (int tile = blockIdx.x; tile < NTILES; tile += GRID_P) {
        int row0 = tile * 128;

        float acc[2][8][4];
        #pragma unroll
        for (int mi = 0; mi < 2; mi++)
            #pragma unroll
            for (int ni = 0; ni < 8; ni++)
                #pragma unroll
                for (int r = 0; r < 4; r++) acc[mi][ni][r] = 0.f;

        #pragma unroll
        for (int c = 0; c < 4; c++) {
            // prefetch: next chunk, or next tile's chunk 0 (OOR rows load zeros)
            if (c < 3) load_chunk(sr, c + 1, row0);
            else       load_chunk(sr, 0, row0 + GRID_P * 128);

            const char* Ah = smem + L_SM_A + (c & 1) * 36864;
            const char* Al = Ah + 18432;
            const char* Bh = smem + L_SM_W + (size_t)c * 18432;
            const char* Bl = smem + L_SM_W + (size_t)(4 + c) * 18432;

            #pragma unroll
            for (int ks = 0; ks < 4; ks++) {
                int kb = (ks * 16 + 2 * q) * 2;
                uint32_t ah[2][4], al[2][4];
                #pragma unroll
                for (int mi = 0; mi < 2; mi++) {
                    int rb = (wm * 32 + mi * 16 + g) * 144 + kb;
                    ah[mi][0] = *(const uint32_t*)(Ah + rb);
                    ah[mi][1] = *(const uint32_t*)(Ah + rb + 8 * 144);
                    ah[mi][2] = *(const uint32_t*)(Ah + rb + 16);
                    ah[mi][3] = *(const uint32_t*)(Ah + rb + 8 * 144 + 16);
                    al[mi][0] = *(const uint32_t*)(Al + rb);
                    al[mi][1] = *(const uint32_t*)(Al + rb + 8 * 144);
                    al[mi][2] = *(const uint32_t*)(Al + rb + 16);
                    al[mi][3] = *(const uint32_t*)(Al + rb + 8 * 144 + 16);
                }
                #pragma unroll
                for (int ni = 0; ni < 8; ni++) {
                    int nb = (wn * 64 + ni * 8 + g) * 144 + kb;
                    uint32_t bh[2], bl[2];
                    bh[0] = *(const uint32_t*)(Bh + nb);
                    bh[1] = *(const uint32_t*)(Bh + nb + 16);
                    bl[0] = *(const uint32_t*)(Bl + nb);
                    bl[1] = *(const uint32_t*)(Bl + nb + 16);
                    #pragma unroll
                    for (int mi = 0; mi < 2; mi++) {
                        mma_bf16(acc[mi][ni], ah[mi], bh);
                        mma_bf16(acc[mi][ni], al[mi], bh);
                        mma_bf16(acc[mi][ni], ah[mi], bl);
                    }
                }
            }

            // store prefetched chunk into its buffer, sync before it is consumed
            {
                char* AHn = smem + L_SM_A + ((c + 1) & 1) * 36864;
                stage_store(sr, AHn, AHn + 18432, t);
                __syncthreads();
            }
        }

        // epilogue: bias + mish -> fp32 h (optional) + bf16 hi/lo planes
        const float* bsm = (const float*)smem;
        #pragma unroll
        for (int mi = 0; mi < 2; mi++) {
            #pragma unroll
            for (int ni = 0; ni < 8; ni++) {
                int col = wn * 64 + ni * 8 + 2 * q;
                float b0 = bsm[col], b1 = bsm[col + 1];
                int rlo = row0 + wm * 32 + mi * 16 + g;
                int rhi = rlo + 8;
                if (rlo < NN) {
                    float o0 = mish2(acc[mi][ni][0] + b0);
                    float o1 = mish2(acc[mi][ni][1] + b1);
                    if (write_f32) *(float2*)&hout[rlo * 128 + col] = make_float2(o0, o1);
                    uint32_t hh, ll;
                    split2(o0, o1, hh, ll);
                    *(uint32_t*)&outH[rlo * 128 + col] = hh;
                    *(uint32_t*)&outL[rlo * 128 + col] = ll;
                }
                if (rhi < NN) {
                    float o0 = mish2(acc[mi][ni][2] + b0);
                    float o1 = mish2(acc[mi][ni][3] + b1);
                    if (write_f32) *(float2*)&hout[rhi * 128 + col] = make_float2(o0, o1);
                    uint32_t hh, ll;
                    split2(o0, o1, hh, ll);
                    *(uint32_t*)&outH[rhi * 128 + col] = hh;
                    *(uint32_t*)&outL[rhi * 128 + col] = ll;
                }
            }
        }
    }
}

// ================= persistent pipelined head: out = h @ Wh^T + b =================
// smem: bias 512 | A double-buffer 4x18432 | W 36864 => 111104 B
#define H_SM_A    512
#define H_SM_W    (512 + 4 * 18432)
#define H_SMEM_BYTES (H_SM_W + 36864)

__global__ __launch_bounds__(256, 1) void k_head_tc(
    const uint16_t* __restrict__ xH, const uint16_t* __restrict__ xL,
    const uint16_t* __restrict__ wprep, const float* __restrict__ bias,
    float* __restrict__ outp) {
    extern __shared__ __align__(16) char smem[];
    int t = threadIdx.x;
    int wid = t >> 5, lane = t & 31;
    int g = lane >> 2, q = lane & 3;

    {
        const uint4* src = (const uint4*)wprep;
        uint4* dst = (uint4*)(smem + H_SM_W);
        #pragma unroll
        for (int it = 0; it < 9; it++) dst[t + it * 256] = src[t + it * 256];
    }
    if (t < 64) ((float*)smem)[t] = bias[t];

    StageRegs sr;
    stage_load_planes(sr, xH, xL, blockIdx.x * 128, 0, t);
    stage_store(sr, smem + H_SM_A, smem + H_SM_A + 18432, t);
    __syncthreads();

    for (int tile = blockIdx.x; tile < NTILES; tile += GRID_P) {
        int row0 = tile * 128;

        float acc[8][4];
        #pragma unroll
        for (int ni = 0; ni < 8; ni++)
            #pragma unroll
            for (int r = 0; r < 4; r++) acc[ni][r] = 0.f;

        #pragma unroll
        for (int c = 0; c < 2; c++) {
            if (c < 1) stage_load_planes(sr, xH, xL, row0, 64, t);
            else       stage_load_planes(sr, xH, xL, row0 + GRID_P * 128, 0, t);

            const char* Ah = smem + H_SM_A + (c & 1) * 36864;
            const char* Al = Ah + 18432;
            const char* Bh = smem + H_SM_W + (size_t)c * 9216;
            const char* Bl = smem + H_SM_W + (size_t)(2 + c) * 9216;

            #pragma unroll
            for (int ks = 0; ks < 4; ks++) {
                int kb = (ks * 16 + 2 * q) * 2;
                uint32_t ah[4], al[4];
                int rb = (wid * 16 + g) * 144 + kb;
                ah[0] = *(const uint32_t*)(Ah + rb);
                ah[1] = *(const uint32_t*)(Ah + rb + 8 * 144);
                ah[2] = *(const uint32_t*)(Ah + rb + 16);
                ah[3] = *(const uint32_t*)(Ah + rb + 8 * 144 + 16);
                al[0] = *(const uint32_t*)(Al + rb);
                al[1] = *(const uint32_t*)(Al + rb + 8 * 144);
                al[2] = *(const uint32_t*)(Al + rb + 16);
                al[3] = *(const uint32_t*)(Al + rb + 8 * 144 + 16);
                #pragma unroll
                for (int ni = 0; ni < 8; ni++) {
                    int nb = (ni * 8 + g) * 144 + kb;
                    uint32_t bh[2], bl[2];
                    bh[0] = *(const uint32_t*)(Bh + nb);
                    bh[1] = *(const uint32_t*)(Bh + nb + 16);
                    bl[0] = *(const uint32_t*)(Bl + nb);
                    bl[1] = *(const uint32_t*)(Bl + nb + 16);
                    mma_bf16(acc[ni], ah, bh);
                    mma_bf16(acc[ni], al, bh);
                    mma_bf16(acc[ni], ah, bl);
                }
            }

            {
                char* AHn = smem + H_SM_A + ((c + 1) & 1) * 36864;
                stage_store(sr, AHn, AHn + 18432, t);
                __syncthreads();
            }
        }

        const float* bsm = (const float*)smem;
        #pragma unroll
        for (int ni = 0; ni < 8; ni++) {
            int col = ni * 8 + 2 * q;
            float b0 = bsm[col], b1 = bsm[col + 1];
            int rlo = row0 + wid * 16 + g;
            int rhi = rlo + 8;
            if (rlo < NN)
                *(float2*)&outp[rlo * 64 + col] =
                    make_float2(acc[ni][0] + b0, acc[ni][1] + b1);
            if (rhi < NN)
                *(float2*)&outp[rhi * 64 + col] =
                    make_float2(acc[ni][2] + b0, acc[ni][3] + b1);
        }
    }
}

// ---------------- launch ----------------
extern "C" void kernel_launch(void* const* d_in, const int* in_sizes, int n_in,
                              void* d_out, int out_size) {
    (void)in_sizes; (void)n_in; (void)out_size;
    const float* x      = (const float*)d_in[0];
    const int*   edge   = (const int*)d_in[1];     // int32 on device (JAX x64 off)
    const float* W_l0   = (const float*)d_in[2];
    const float* b_l0   = (const float*)d_in[3];
    const float* W_r0   = (const float*)d_in[4];
    const float* W_l1   = (const float*)d_in[5];
    const float* b_l1   = (const float*)d_in[6];
    const float* W_r1   = (const float*)d_in[7];
    const float* W_head = (const float*)d_in[8];
    const float* b_head = (const float*)d_in[9];
    float* out = (float*)d_out;

    cudaFuncSetAttribute(k_layer_tc, cudaFuncAttributeMaxDynamicSharedMemorySize,
                         L_SMEM_BYTES);
    cudaFuncSetAttribute(k_head_tc, cudaFuncAttributeMaxDynamicSharedMemorySize,
                         H_SMEM_BYTES);

    float *h_p;
    uint16_t *aggH_p, *aggL_p, *xH_p, *xL_p, *wb0_p, *wb1_p, *wbh_p;
    cudaGetSymbolAddress((void**)&h_p,    g_h);
    cudaGetSymbolAddress((void**)&aggH_p, g_aggH);
    cudaGetSymbolAddress((void**)&aggL_p, g_aggL);
    cudaGetSymbolAddress((void**)&xH_p,   g_xH);
    cudaGetSymbolAddress((void**)&xL_p,   g_xL);
    cudaGetSymbolAddress((void**)&wb0_p,  g_WB0);
    cudaGetSymbolAddress((void**)&wb1_p,  g_WB1);
    cudaGetSymbolAddress((void**)&wbh_p,  g_WBh);

    int agg_grid = (NN * 32 + 255) / 256;

    // launch order chosen so launch #5 (ncu -s 5 -c 1) is k_aggregate
    k_zero_counts<<<(NN + 255) / 256, 256>>>();                                   // 0
    k_hist<<<EE / 256, 256>>>(edge);                                              // 1
    k_scan<<<NB_SCAN, 512>>>();                                                   // 2
    k_scatter<<<EE / 256, 256>>>(edge);                                           // 3
    k_prep_all<<<72, 256>>>(W_l0, W_r0, W_l1, W_r1, W_head);                      // 4
    k_aggregate<<<agg_grid, 256>>>(x, aggH_p, aggL_p);                            // 5 <- profiled
    k_layer_tc<<<GRID_P, 256, L_SMEM_BYTES>>>(aggH_p, aggL_p, nullptr, nullptr, x,
                                              wb0_p, b_l0, h_p, xH_p, xL_p, 1);   // 6
    k_aggregate<<<agg_grid, 256>>>(h_p, aggH_p, aggL_p);                          // 7
    k_layer_tc<<<GRID_P, 256, L_SMEM_BYTES>>>(aggH_p, aggL_p, xH_p, xL_p, nullptr,
                                              wb1_p, b_l1, h_p, xH_p, xL_p, 0);   // 8
    k_head_tc<<<GRID_P, 256, H_SMEM_BYTES>>>(xH_p, xL_p, wbh_p, b_head, out);     // 9
}

// round 10
// speedup vs baseline: 2.0792x; 1.0228x over previous
#include <cuda_runtime.h>
#include <cuda_bf16.h>
#include <cstdint>

#define NN 100000
#define EE 1600000
#define DH 128
#define NTILES ((NN + 127) / 128)   // 782
#define GRID_P 148
#define NB_SCAN ((NN + 511) / 512)  // 196

// ---------------- device scratch ----------------
__device__ __align__(16) uint16_t g_aggH[NN * DH];
__device__ __align__(16) uint16_t g_aggL[NN * DH];
__device__ __align__(16) uint16_t g_xH[NN * DH];
__device__ __align__(16) uint16_t g_xL[NN * DH];
__device__ float g_h[NN * DH];
__device__ int   g_cnt[NN];          // zero-init at load; re-zeroed by k_head_tc tail
__device__ int   g_cur[NN];
__device__ int   g_off[NN];
__device__ int   g_srcsorted[EE];
__device__ unsigned long long g_pkt[NB_SCAN];
__device__ __align__(16) uint16_t g_WB0[2 * 4 * 128 * 72];
__device__ __align__(16) uint16_t g_WB1[2 * 4 * 128 * 72];
__device__ __align__(16) uint16_t g_WBh[2 * 2 * 64 * 72];

// ---------------- helpers ----------------
__device__ __forceinline__ void split2(float a, float b, uint32_t& h, uint32_t& l) {
    __nv_bfloat16 ha = __float2bfloat16_rn(a);
    __nv_bfloat16 hb = __float2bfloat16_rn(b);
    __nv_bfloat16 la = __float2bfloat16_rn(a - __bfloat162float(ha));
    __nv_bfloat16 lb = __float2bfloat16_rn(b - __bfloat162float(hb));
    h = (uint32_t)__bfloat16_as_ushort(ha) | ((uint32_t)__bfloat16_as_ushort(hb) << 16);
    l = (uint32_t)__bfloat16_as_ushort(la) | ((uint32_t)__bfloat16_as_ushort(lb) << 16);
}
__device__ __forceinline__ float mish2(float v) {
    float t = __expf(fminf(v, 30.f));
    float r = t * t + 2.f * t;
    return v * (r / (r + 2.f));
}
__device__ __forceinline__ void mma_bf16(float* c, const uint32_t* a, const uint32_t* b) {
    asm volatile(
        "mma.sync.aligned.m16n8k16.row.col.f32.bf16.bf16.f32 "
        "{%0,%1,%2,%3}, {%4,%5,%6,%7}, {%8,%9}, {%0,%1,%2,%3};"
        : "+f"(c[0]), "+f"(c[1]), "+f"(c[2]), "+f"(c[3])
        : "r"(a[0]), "r"(a[1]), "r"(a[2]), "r"(a[3]), "r"(b[0]), "r"(b[1]));
}
__device__ __forceinline__ void ldsm4(uint32_t* r, uint32_t a) {
    asm volatile("ldmatrix.sync.aligned.m8n8.x4.shared.b16 {%0,%1,%2,%3}, [%4];"
        : "=r"(r[0]), "=r"(r[1]), "=r"(r[2]), "=r"(r[3]) : "r"(a));
}

// ---------------- edge preprocessing ----------------
__global__ void k_hist(const int* __restrict__ edge) {
    int e = blockIdx.x * blockDim.x + threadIdx.x;
    if (e < EE) atomicAdd(&g_cnt[edge[EE + e]], 1);
}
// single-pass decoupled-lookback exclusive scan of g_cnt -> g_off
__global__ void k_scan() {
    __shared__ int s[512];
    __shared__ int s_prefix;
    int t = threadIdx.x, b = blockIdx.x;
    int i = b * 512 + t;
    int v = (i < NN) ? g_cnt[i] : 0;
    s[t] = v;
    __syncthreads();
    #pragma unroll
    for (int off = 1; off < 512; off <<= 1) {
        int add = (t >= off) ? s[t - off] : 0;
        __syncthreads();
        s[t] += add;
        __syncthreads();
    }
    int total = s[511];
    if (t == 0) {
        atomicExch(&g_pkt[b], (1ull << 62) | (unsigned long long)total);
        long long prefix = 0;
        for (int j = b - 1; j >= 0; j--) {
            unsigned long long p;
            do { p = atomicAdd(&g_pkt[j], 0ull); } while ((p >> 62) == 0ull);
            prefix += (long long)(p & 0x3FFFFFFFFFFFFFFFull);
            if ((p >> 62) == 2ull) break;
        }
        atomicExch(&g_pkt[b], (2ull << 62) | (unsigned long long)(prefix + total));
        s_prefix = (int)prefix;
    }
    __syncthreads();
    if (i < NN) g_off[i] = s[t] - v + s_prefix;
}
__global__ void k_scatter(const int* __restrict__ edge) {
    int e = blockIdx.x * blockDim.x + threadIdx.x;
    if (e < EE) {
        int src = edge[e];
        int dst = edge[EE + e];
        int pos = g_off[dst] + atomicAdd(&g_cur[dst], 1);
        g_srcsorted[pos] = src;
    }
}

// ---------------- aggregation: shfl-batched, emits normalized bf16 planes ----------------
__global__ __launch_bounds__(256) void k_aggregate(const float* __restrict__ feat,
                                                   uint16_t* __restrict__ outH,
                                                   uint16_t* __restrict__ outL) {
    int w = (blockIdx.x * blockDim.x + threadIdx.x) >> 5;
    if (w >= NN) return;
    int lane = threadIdx.x & 31;
    int start = g_off[w];
    int c = g_cnt[w];
    const float4* f4 = (const float4*)feat;
    float4 acc = make_float4(0.f, 0.f, 0.f, 0.f);
    for (int base = 0; base < c; base += 32) {
        int idx = (base + lane < c) ? g_srcsorted[start + base + lane] : 0;
        int m = min(32, c - base);
        #pragma unroll 4
        for (int j = 0; j < m; j++) {
            int s = __shfl_sync(0xffffffffu, idx, j);
            float4 v = __ldg(&f4[s * 32 + lane]);
            acc.x += v.x; acc.y += v.y; acc.z += v.z; acc.w += v.w;
        }
    }
    float inv = 1.f / fmaxf((float)c, 1.f);
    acc.x *= inv; acc.y *= inv; acc.z *= inv; acc.w *= inv;
    uint32_t h01, h23, l01, l23;
    split2(acc.x, acc.y, h01, l01);
    split2(acc.z, acc.w, h23, l23);
    *(uint2*)&outH[w * 128 + lane * 4] = make_uint2(h01, h23);
    *(uint2*)&outL[w * 128 + lane * 4] = make_uint2(l01, l23);
}

// ---------------- fused weight prep (one launch) ----------------
__device__ __forceinline__ void prep_layer_elem(const float* Wl, const float* Wr,
                                                uint16_t* outw, int idx) {
    int n = idx >> 6;
    int kg = (idx & 63) * 4;
    const float* Ws = (kg < 128) ? Wl : Wr;
    float4 v = *(const float4*)&Ws[n * 128 + (kg & 127)];
    uint32_t h01, h23, l01, l23;
    split2(v.x, v.y, h01, l01);
    split2(v.z, v.w, h23, l23);
    int c = kg >> 6, kk = kg & 63;
    *(uint2*)&outw[((0 * 4 + c) * 128 + n) * 72 + kk] = make_uint2(h01, h23);
    *(uint2*)&outw[((4 + c) * 128 + n) * 72 + kk]     = make_uint2(l01, l23);
}
__global__ void k_prep_all(const float* __restrict__ Wl0, const float* __restrict__ Wr0,
                           const float* __restrict__ Wl1, const float* __restrict__ Wr1,
                           const float* __restrict__ Wh) {
    int b = blockIdx.x;
    int t = threadIdx.x;
    if (b < 32) {
        prep_layer_elem(Wl0, Wr0, g_WB0, b * 256 + t);
    } else if (b < 64) {
        prep_layer_elem(Wl1, Wr1, g_WB1, (b - 32) * 256 + t);
    } else {
        int idx = (b - 64) * 256 + t;
        int n = idx >> 5;
        int kg = (idx & 31) * 4;
        float4 v = *(const float4*)&Wh[n * 128 + kg];
        uint32_t h01, h23, l01, l23;
        split2(v.x, v.y, h01, l01);
        split2(v.z, v.w, h23, l23);
        int c = kg >> 6, kk = kg & 63;
        *(uint2*)&g_WBh[((0 * 2 + c) * 64 + n) * 72 + kk] = make_uint2(h01, h23);
        *(uint2*)&g_WBh[((2 + c) * 64 + n) * 72 + kk]     = make_uint2(l01, l23);
    }
}

// ---------------- staging primitives ----------------
struct StageRegs { uint4 rH[4], rL[4]; };

__device__ __forceinline__ void stage_load_planes(StageRegs& s, const uint16_t* pH,
                                                  const uint16_t* pL, int row0, int cb,
                                                  int t) {
    #pragma unroll
    for (int i = 0; i < 4; i++) {
        int v = t + i * 256, row = v >> 3, f = v & 7, gr = row0 + row;
        if (gr < NN) {
            s.rH[i] = *(const uint4*)(pH + gr * 128 + cb + f * 8);
            s.rL[i] = *(const uint4*)(pL + gr * 128 + cb + f * 8);
        } else {
            s.rH[i] = make_uint4(0, 0, 0, 0);
            s.rL[i] = make_uint4(0, 0, 0, 0);
        }
    }
}
__device__ __forceinline__ void stage_load_f32(StageRegs& s, const float* xf,
                                               int row0, int cb16, int t) {
    const float4* x4 = (const float4*)xf;
    #pragma unroll
    for (int i = 0; i < 4; i++) {
        int v = t + i * 256, row = v >> 3, f = v & 7, gr = row0 + row;
        float4 a = make_float4(0.f, 0.f, 0.f, 0.f);
        float4 b = make_float4(0.f, 0.f, 0.f, 0.f);
        if (gr < NN) {
            a = x4[gr * 32 + cb16 + f * 2];
            b = x4[gr * 32 + cb16 + f * 2 + 1];
        }
        uint32_t h01, h23, h45, h67, l01, l23, l45, l67;
        split2(a.x, a.y, h01, l01);
        split2(a.z, a.w, h23, l23);
        split2(b.x, b.y, h45, l45);
        split2(b.z, b.w, h67, l67);
        s.rH[i] = make_uint4(h01, h23, h45, h67);
        s.rL[i] = make_uint4(l01, l23, l45, l67);
    }
}
__device__ __forceinline__ void stage_store(const StageRegs& s, char* AH, char* AL, int t) {
    #pragma unroll
    for (int i = 0; i < 4; i++) {
        int v = t + i * 256, row = v >> 3, f = v & 7;
        *(uint4*)(AH + row * 144 + f * 16) = s.rH[i];
        *(uint4*)(AL + row * 144 + f * 16) = s.rL[i];
    }
}

// ================= persistent pipelined mma.sync fused SAGE layer (ldmatrix) =========
// smem: bias 512 | A double-buffer 2x(18432+18432) | W 147456  => 221696 B
#define L_SM_A    512
#define L_SM_W    (512 + 4 * 18432)
#define L_SMEM_BYTES (L_SM_W + 147456)

__global__ __launch_bounds__(256, 1) void k_layer_tc(
    const uint16_t* __restrict__ aggH, const uint16_t* __restrict__ aggL,
    const uint16_t* xH, const uint16_t* xL,
    const float* __restrict__ xf32,
    const uint16_t* __restrict__ wprep, const float* __restrict__ bias,
    float* __restrict__ hout, uint16_t* outH, uint16_t* outL, int write_f32) {
    extern __shared__ __align__(16) char smem[];
    int t = threadIdx.x;
    int wid = t >> 5, lane = t & 31;
    int g = lane >> 2, q = lane & 3;
    int wm = wid & 3, wn = wid >> 2;

    {
        const uint4* src = (const uint4*)wprep;
        uint4* dst = (uint4*)(smem + L_SM_W);
        #pragma unroll
        for (int it = 0; it < 36; it++) dst[t + it * 256] = src[t + it * 256];
    }
    if (t < 128) ((float*)smem)[t] = bias[t];

    // ldmatrix per-lane byte offsets (within a 16x16 / n16k16 fragment tile)
    uint32_t smemS = (uint32_t)__cvta_generic_to_shared(smem);
    int tile4 = lane >> 3, r8 = lane & 7;
    uint32_t laneA = (uint32_t)((((tile4 & 1) * 8 + r8) * 144) + (tile4 >> 1) * 16);
    uint32_t laneB = (uint32_t)((((tile4 >> 1) * 8 + r8) * 144) + (tile4 & 1) * 16);
    uint32_t aRow0 = (uint32_t)((wm * 32) * 144);          // mi adds 16*144
    uint32_t bRow0 = (uint32_t)((wn * 64) * 144);          // nip adds 16*144

    auto load_chunk = [&](StageRegs& s, int cc, int r0) {
        if (cc < 2)
            stage_load_planes(s, aggH, aggL, r0, cc * 64, t);
        else if (xf32)
            stage_load_f32(s, xf32, r0, (cc - 2) * 16, t);
        else
            stage_load_planes(s, xH, xL, r0, (cc - 2) * 64, t);
    };

    StageRegs sr;
    load_chunk(sr, 0, blockIdx.x * 128);
    stage_store(sr, smem + L_SM_A, smem + L_SM_A + 18432, t);
    __syncthreads();

    for (int tile = blockIdx.x; tile < NTILES; tile += GRID_P) {
        int row0 = tile * 128;

        float acc[2][8][4];
        #pragma unroll
        for (int mi = 0; mi < 2; mi++)
            #pragma unroll
            for (int ni = 0; ni < 8; ni++)
                #pragma unroll
                for (int r = 0; r < 4; r++) acc[mi][ni][r] = 0.f;

        #pragma unroll
        for (int c = 0; c < 4; c++) {
            if (c < 3) load_chunk(sr, c + 1, row0);
            else       load_chunk(sr, 0, row0 + GRID_P * 128);

            uint32_t AhS = smemS + L_SM_A + (c & 1) * 36864 + aRow0 + laneA;
            uint32_t AlS = AhS + 18432;
            uint32_t BhS = smemS + L_SM_W + c * 18432 + bRow0 + laneB;
            uint32_t BlS = BhS + 4 * 18432;

            #pragma unroll
            for (int ks = 0; ks < 4; ks++) {
                uint32_t ksb = ks * 32;
                uint32_t ah[2][4], al[2][4];
                ldsm4(ah[0], AhS + ksb);
                ldsm4(ah[1], AhS + 16 * 144 + ksb);
                ldsm4(al[0], AlS + ksb);
                ldsm4(al[1], AlS + 16 * 144 + ksb);
                #pragma unroll
                for (int nip = 0; nip < 4; nip++) {
                    uint32_t bh[4], bl[4];
                    ldsm4(bh, BhS + nip * (16 * 144) + ksb);
                    ldsm4(bl, BlS + nip * (16 * 144) + ksb);
                    #pragma unroll
                    for (int mi = 0; mi < 2; mi++) {
                        mma_bf16(acc[mi][2 * nip],     ah[mi], bh);
                        mma_bf16(acc[mi][2 * nip],     al[mi], bh);
                        mma_bf16(acc[mi][2 * nip],     ah[mi], bl);
                        mma_bf16(acc[mi][2 * nip + 1], ah[mi], bh + 2);
                        mma_bf16(acc[mi][2 * nip + 1], al[mi], bh + 2);
                        mma_bf16(acc[mi][2 * nip + 1], ah[mi], bl + 2);
                    }
                }
            }

            {
                char* AHn = smem + L_SM_A + ((c + 1) & 1) * 36864;
                stage_store(sr, AHn, AHn + 18432, t);
                __syncthreads();
            }
        }

        const float* bsm = (const float*)smem;
        #pragma unroll
        for (int mi = 0; mi < 2; mi++) {
            #pragma unroll
            for (int ni = 0; ni < 8; ni++) {
                int col = wn * 64 + ni * 8 + 2 * q;
                float b0 = bsm[col], b1 = bsm[col + 1];
                int rlo = row0 + wm * 32 + mi * 16 + g;
                int rhi = rlo + 8;
                if (rlo < NN) {
                    float o0 = mish2(acc[mi][ni][0] + b0);
                    float o1 = mish2(acc[mi][ni][1] + b1);
                    if (write_f32) *(float2*)&hout[rlo * 128 + col] = make_float2(o0, o1);
                    uint32_t hh, ll;
                    split2(o0, o1, hh, ll);
                    *(uint32_t*)&outH[rlo * 128 + col] = hh;
                    *(uint32_t*)&outL[rlo * 128 + col] = ll;
                }
                if (rhi < NN) {
                    float o0 = mish2(acc[mi][ni][2] + b0);
                    float o1 = mish2(acc[mi][ni][3] + b1);
                    if (write_f32) *(float2*)&hout[rhi * 128 + col] = make_float2(o0, o1);
                    uint32_t hh, ll;
                    split2(o0, o1, hh, ll);
                    *(uint32_t*)&outH[rhi * 128 + col] = hh;
                    *(uint32_t*)&outL[rhi * 128 + col] = ll;
                }
            }
        }
    }
}

// ================= persistent pipelined head (ldmatrix): out = h @ Wh^T + b =========
// smem: bias 512 | A double-buffer 4x18432 | W 36864 => 111104 B
#define H_SM_A    512
#define H_SM_W    (512 + 4 * 18432)
#define H_SMEM_BYTES (H_SM_W + 36864)

__global__ __launch_bounds__(256, 1) void k_head_tc(
    const uint16_t* __restrict__ xH, const uint16_t* __restrict__ xL,
    const uint16_t* __restrict__ wprep, const float* __restrict__ bias,
    float* __restrict__ outp) {
    extern __shared__ __align__(16) char smem[];
    int t = threadIdx.x;
    int wid = t >> 5, lane = t & 31;
    int g = lane >> 2, q = lane & 3;

    {
        const uint4* src = (const uint4*)wprep;
        uint4* dst = (uint4*)(smem + H_SM_W);
        #pragma unroll
        for (int it = 0; it < 9; it++) dst[t + it * 256] = src[t + it * 256];
    }
    if (t < 64) ((float*)smem)[t] = bias[t];

    uint32_t smemS = (uint32_t)__cvta_generic_to_shared(smem);
    int tile4 = lane >> 3, r8 = lane & 7;
    uint32_t laneA = (uint32_t)((((tile4 & 1) * 8 + r8) * 144) + (tile4 >> 1) * 16);
    uint32_t laneB = (uint32_t)((((tile4 >> 1) * 8 + r8) * 144) + (tile4 & 1) * 16);
    uint32_t aRow0 = (uint32_t)((wid * 16) * 144);

    StageRegs sr;
    stage_load_planes(sr, xH, xL, blockIdx.x * 128, 0, t);
    stage_store(sr, smem + H_SM_A, smem + H_SM_A + 18432, t);
    __syncthreads();

    for (int tile = blockIdx.x; tile < NTILES; tile += GRID_P) {
        int row0 = tile * 128;

        float acc[8][4];
        #pragma unroll
        for (int ni = 0; ni < 8; ni++)
            #pragma unroll
            for (int r = 0; r < 4; r++) acc[ni][r] = 0.f;

        #pragma unroll
        for (int c = 0; c < 2; c++) {
            if (c < 1) stage_load_planes(sr, xH, xL, row0, 64, t);
            else       stage_load_planes(sr, xH, xL, row0 + GRID_P * 128, 0, t);

            uint32_t AhS = smemS + H_SM_A + (c & 1) * 36864 + aRow0 + laneA;
            uint32_t AlS = AhS + 18432;
            uint32_t BhS = smemS + H_SM_W + c * 9216 + laneB;
            uint32_t BlS = BhS + 2 * 9216;

            #pragma unroll
            for (int ks = 0; ks < 4; ks++) {
                uint32_t ksb = ks * 32;
                uint32_t ah[4], al[4];
                ldsm4(ah, AhS + ksb);
                ldsm4(al, AlS + ksb);
                #pragma unroll
                for (int nip = 0; nip < 4; nip++) {
                    uint32_t bh[4], bl[4];
                    ldsm4(bh, BhS + nip * (16 * 144) + ksb);
                    ldsm4(bl, BlS + nip * (16 * 144) + ksb);
                    mma_bf16(acc[2 * nip],     ah, bh);
                    mma_bf16(acc[2 * nip],     al, bh);
                    mma_bf16(acc[2 * nip],     ah, bl);
                    mma_bf16(acc[2 * nip + 1], ah, bh + 2);
                    mma_bf16(acc[2 * nip + 1], al, bh + 2);
                    mma_bf16(acc[2 * nip + 1], ah, bl + 2);
                }
            }

            {
                char* AHn = smem + H_SM_A + ((c + 1) & 1) * 36864;
                stage_store(sr, AHn, AHn + 18432, t);
                __syncthreads();
            }
        }

        const float* bsm = (const float*)smem;
        #pragma unroll
        for (int ni = 0; ni < 8; ni++) {
            int col = ni * 8 + 2 * q;
            float b0 = bsm[col], b1 = bsm[col + 1];
            int rlo = row0 + wid * 16 + g;
            int rhi = rlo + 8;
            if (rlo < NN)
                *(float2*)&outp[rlo * 64 + col] =
                    make_float2(acc[ni][0] + b0, acc[ni][1] + b1);
            if (rhi < NN)
                *(float2*)&outp[rhi * 64 + col] =
                    make_float2(acc[ni][2] + b0, acc[ni][3] + b1);
        }
    }

    // tail: re-zero counters for the next graph replay (this kernel is last)
    int gtid = blockIdx.x * 256 + t;
    for (int i = gtid; i < NN; i += GRID_P * 256) { g_cnt[i] = 0; g_cur[i] = 0; }
    if (gtid < NB_SCAN) g_pkt[gtid] = 0ull;
}

// ---------------- launch ----------------
extern "C" void kernel_launch(void* const* d_in, const int* in_sizes, int n_in,
                              void* d_out, int out_size) {
    (void)in_sizes; (void)n_in; (void)out_size;
    const float* x      = (const float*)d_in[0];
    const int*   edge   = (const int*)d_in[1];     // int32 on device (JAX x64 off)
    const float* W_l0   = (const float*)d_in[2];
    const float* b_l0   = (const float*)d_in[3];
    const float* W_r0   = (const float*)d_in[4];
    const float* W_l1   = (const float*)d_in[5];
    const float* b_l1   = (const float*)d_in[6];
    const float* W_r1   = (const float*)d_in[7];
    const float* W_head = (const float*)d_in[8];
    const float* b_head = (const float*)d_in[9];
    float* out = (float*)d_out;

    cudaFuncSetAttribute(k_layer_tc, cudaFuncAttributeMaxDynamicSharedMemorySize,
                         L_SMEM_BYTES);
    cudaFuncSetAttribute(k_head_tc, cudaFuncAttributeMaxDynamicSharedMemorySize,
                         H_SMEM_BYTES);

    float *h_p;
    uint16_t *aggH_p, *aggL_p, *xH_p, *xL_p, *wb0_p, *wb1_p, *wbh_p;
    cudaGetSymbolAddress((void**)&h_p,    g_h);
    cudaGetSymbolAddress((void**)&aggH_p, g_aggH);
    cudaGetSymbolAddress((void**)&aggL_p, g_aggL);
    cudaGetSymbolAddress((void**)&xH_p,   g_xH);
    cudaGetSymbolAddress((void**)&xL_p,   g_xL);
    cudaGetSymbolAddress((void**)&wb0_p,  g_WB0);
    cudaGetSymbolAddress((void**)&wb1_p,  g_WB1);
    cudaGetSymbolAddress((void**)&wbh_p,  g_WBh);

    int agg_grid = (NN * 32 + 255) / 256;

    // counters are zero at load and re-zeroed by k_head_tc's tail each call.
    // launch index 3 (the ncu-profiled slot) is now k_aggregate.
    k_hist<<<EE / 256, 256>>>(edge);                                              // 0
    k_scan<<<NB_SCAN, 512>>>();                                                   // 1
    k_scatter<<<EE / 256, 256>>>(edge);                                           // 2
    k_aggregate<<<agg_grid, 256>>>(x, aggH_p, aggL_p);                            // 3 <- profiled
    k_prep_all<<<72, 256>>>(W_l0, W_r0, W_l1, W_r1, W_head);                      // 4
    k_layer_tc<<<GRID_P, 256, L_SMEM_BYTES>>>(aggH_p, aggL_p, nullptr, nullptr, x,
                                              wb0_p, b_l0, h_p, xH_p, xL_p, 1);   // 5
    k_aggregate<<<agg_grid, 256>>>(h_p, aggH_p, aggL_p);                          // 6
    k_layer_tc<<<GRID_P, 256, L_SMEM_BYTES>>>(aggH_p, aggL_p, xH_p, xL_p, nullptr,
                                              wb1_p, b_l1, h_p, xH_p, xL_p, 0);   // 7
    k_head_tc<<<GRID_P, 256, H_SMEM_BYTES>>>(xH_p, xL_p, wbh_p, b_head, out);     // 8
}

// round 11
// speedup vs baseline: 2.1259x; 1.0225x over previous
#include <cuda_runtime.h>
#include <cuda_bf16.h>
#include <cstdint>

#define NN 100000
#define EE 1600000
#define DH 128
#define NTILES ((NN + 127) / 128)   // 782
#define GRID_P 148
#define NB_SCAN ((NN + 511) / 512)  // 196
#define HIST_BLOCKS (EE / 256)      // 6250

// ---------------- device scratch ----------------
__device__ __align__(16) uint16_t g_aggH[NN * DH];
__device__ __align__(16) uint16_t g_aggL[NN * DH];
__device__ __align__(16) uint16_t g_xH[NN * DH];
__device__ __align__(16) uint16_t g_xL[NN * DH];
__device__ float g_h[NN * DH];
__device__ int   g_cnt[NN];          // zero-init at load; re-zeroed by k_head_tc tail
__device__ int   g_cur[NN];
__device__ int   g_off[NN];
__device__ int   g_srcsorted[EE];
__device__ unsigned long long g_pkt[NB_SCAN];
__device__ __align__(16) uint16_t g_WB0[2 * 4 * 128 * 72];
__device__ __align__(16) uint16_t g_WB1[2 * 4 * 128 * 72];
__device__ __align__(16) uint16_t g_WBh[2 * 2 * 64 * 72];

// ---------------- helpers ----------------
__device__ __forceinline__ void split2(float a, float b, uint32_t& h, uint32_t& l) {
    __nv_bfloat16 ha = __float2bfloat16_rn(a);
    __nv_bfloat16 hb = __float2bfloat16_rn(b);
    __nv_bfloat16 la = __float2bfloat16_rn(a - __bfloat162float(ha));
    __nv_bfloat16 lb = __float2bfloat16_rn(b - __bfloat162float(hb));
    h = (uint32_t)__bfloat16_as_ushort(ha) | ((uint32_t)__bfloat16_as_ushort(hb) << 16);
    l = (uint32_t)__bfloat16_as_ushort(la) | ((uint32_t)__bfloat16_as_ushort(lb) << 16);
}
__device__ __forceinline__ float mish2(float v) {
    float t = __expf(fminf(v, 30.f));
    float r = t * t + 2.f * t;
    return v * (r / (r + 2.f));
}
__device__ __forceinline__ void mma_bf16(float* c, const uint32_t* a, const uint32_t* b) {
    asm volatile(
        "mma.sync.aligned.m16n8k16.row.col.f32.bf16.bf16.f32 "
        "{%0,%1,%2,%3}, {%4,%5,%6,%7}, {%8,%9}, {%0,%1,%2,%3};"
        : "+f"(c[0]), "+f"(c[1]), "+f"(c[2]), "+f"(c[3])
        : "r"(a[0]), "r"(a[1]), "r"(a[2]), "r"(a[3]), "r"(b[0]), "r"(b[1]));
}
__device__ __forceinline__ void ldsm4(uint32_t* r, uint32_t a) {
    asm volatile("ldmatrix.sync.aligned.m8n8.x4.shared.b16 {%0,%1,%2,%3}, [%4];"
        : "=r"(r[0]), "=r"(r[1]), "=r"(r[2]), "=r"(r[3]) : "r"(a));
}

// ---------------- fused hist + weight prep ----------------
__device__ __forceinline__ void prep_layer_elem(const float* Wl, const float* Wr,
                                                uint16_t* outw, int idx) {
    int n = idx >> 6;
    int kg = (idx & 63) * 4;
    const float* Ws = (kg < 128) ? Wl : Wr;
    float4 v = *(const float4*)&Ws[n * 128 + (kg & 127)];
    uint32_t h01, h23, l01, l23;
    split2(v.x, v.y, h01, l01);
    split2(v.z, v.w, h23, l23);
    int c = kg >> 6, kk = kg & 63;
    *(uint2*)&outw[((0 * 4 + c) * 128 + n) * 72 + kk] = make_uint2(h01, h23);
    *(uint2*)&outw[((4 + c) * 128 + n) * 72 + kk]     = make_uint2(l01, l23);
}
__global__ void k_hist_prep(const int* __restrict__ edge,
                            const float* __restrict__ Wl0, const float* __restrict__ Wr0,
                            const float* __restrict__ Wl1, const float* __restrict__ Wr1,
                            const float* __restrict__ Wh) {
    int b = blockIdx.x;
    int t = threadIdx.x;
    if (b < HIST_BLOCKS) {
        int e = b * 256 + t;
        atomicAdd(&g_cnt[edge[EE + e]], 1);
    } else {
        int pb = b - HIST_BLOCKS;    // 0..71
        if (pb < 32) {
            prep_layer_elem(Wl0, Wr0, g_WB0, pb * 256 + t);
        } else if (pb < 64) {
            prep_layer_elem(Wl1, Wr1, g_WB1, (pb - 32) * 256 + t);
        } else {
            int idx = (pb - 64) * 256 + t;
            int n = idx >> 5;
            int kg = (idx & 31) * 4;
            float4 v = *(const float4*)&Wh[n * 128 + kg];
            uint32_t h01, h23, l01, l23;
            split2(v.x, v.y, h01, l01);
            split2(v.z, v.w, h23, l23);
            int c = kg >> 6, kk = kg & 63;
            *(uint2*)&g_WBh[((0 * 2 + c) * 64 + n) * 72 + kk] = make_uint2(h01, h23);
            *(uint2*)&g_WBh[((2 + c) * 64 + n) * 72 + kk]     = make_uint2(l01, l23);
        }
    }
}
// single-pass decoupled-lookback exclusive scan of g_cnt -> g_off
__global__ void k_scan() {
    __shared__ int s[512];
    __shared__ int s_prefix;
    int t = threadIdx.x, b = blockIdx.x;
    int i = b * 512 + t;
    int v = (i < NN) ? g_cnt[i] : 0;
    s[t] = v;
    __syncthreads();
    #pragma unroll
    for (int off = 1; off < 512; off <<= 1) {
        int add = (t >= off) ? s[t - off] : 0;
        __syncthreads();
        s[t] += add;
        __syncthreads();
    }
    int total = s[511];
    if (t == 0) {
        atomicExch(&g_pkt[b], (1ull << 62) | (unsigned long long)total);
        long long prefix = 0;
        for (int j = b - 1; j >= 0; j--) {
            unsigned long long p;
            do { p = atomicAdd(&g_pkt[j], 0ull); } while ((p >> 62) == 0ull);
            prefix += (long long)(p & 0x3FFFFFFFFFFFFFFFull);
            if ((p >> 62) == 2ull) break;
        }
        atomicExch(&g_pkt[b], (2ull << 62) | (unsigned long long)(prefix + total));
        s_prefix = (int)prefix;
    }
    __syncthreads();
    if (i < NN) g_off[i] = s[t] - v + s_prefix;
}
__global__ void k_scatter(const int* __restrict__ edge) {
    int e = blockIdx.x * blockDim.x + threadIdx.x;
    if (e < EE) {
        int src = edge[e];
        int dst = edge[EE + e];
        int pos = g_off[dst] + atomicAdd(&g_cur[dst], 1);
        g_srcsorted[pos] = src;
    }
}

// ---------------- aggregation: MLP-8 batched gathers, emits normalized bf16 planes ----
__global__ __launch_bounds__(256) void k_aggregate(const float* __restrict__ feat,
                                                   uint16_t* __restrict__ outH,
                                                   uint16_t* __restrict__ outL) {
    int w = (blockIdx.x * blockDim.x + threadIdx.x) >> 5;
    if (w >= NN) return;
    int lane = threadIdx.x & 31;
    int start = g_off[w];
    int c = g_cnt[w];
    const float4* f4 = (const float4*)feat;
    float4 acc0 = make_float4(0.f, 0.f, 0.f, 0.f);
    float4 acc1 = make_float4(0.f, 0.f, 0.f, 0.f);
    for (int base = 0; base < c; base += 32) {
        int idx = (base + lane < c) ? g_srcsorted[start + base + lane] : 0;
        int m = min(32, c - base);
        int j = 0;
        for (; j + 8 <= m; j += 8) {
            int s0 = __shfl_sync(0xffffffffu, idx, j + 0);
            int s1 = __shfl_sync(0xffffffffu, idx, j + 1);
            int s2 = __shfl_sync(0xffffffffu, idx, j + 2);
            int s3 = __shfl_sync(0xffffffffu, idx, j + 3);
            int s4 = __shfl_sync(0xffffffffu, idx, j + 4);
            int s5 = __shfl_sync(0xffffffffu, idx, j + 5);
            int s6 = __shfl_sync(0xffffffffu, idx, j + 6);
            int s7 = __shfl_sync(0xffffffffu, idx, j + 7);
            float4 v0 = __ldg(&f4[s0 * 32 + lane]);
            float4 v1 = __ldg(&f4[s1 * 32 + lane]);
            float4 v2 = __ldg(&f4[s2 * 32 + lane]);
            float4 v3 = __ldg(&f4[s3 * 32 + lane]);
            float4 v4 = __ldg(&f4[s4 * 32 + lane]);
            float4 v5 = __ldg(&f4[s5 * 32 + lane]);
            float4 v6 = __ldg(&f4[s6 * 32 + lane]);
            float4 v7 = __ldg(&f4[s7 * 32 + lane]);
            acc0.x += v0.x; acc0.y += v0.y; acc0.z += v0.z; acc0.w += v0.w;
            acc1.x += v1.x; acc1.y += v1.y; acc1.z += v1.z; acc1.w += v1.w;
            acc0.x += v2.x; acc0.y += v2.y; acc0.z += v2.z; acc0.w += v2.w;
            acc1.x += v3.x; acc1.y += v3.y; acc1.z += v3.z; acc1.w += v3.w;
            acc0.x += v4.x; acc0.y += v4.y; acc0.z += v4.z; acc0.w += v4.w;
            acc1.x += v5.x; acc1.y += v5.y; acc1.z += v5.z; acc1.w += v5.w;
            acc0.x += v6.x; acc0.y += v6.y; acc0.z += v6.z; acc0.w += v6.w;
            acc1.x += v7.x; acc1.y += v7.y; acc1.z += v7.z; acc1.w += v7.w;
        }
        for (; j < m; j++) {
            int s = __shfl_sync(0xffffffffu, idx, j);
            float4 v = __ldg(&f4[s * 32 + lane]);
            acc0.x += v.x; acc0.y += v.y; acc0.z += v.z; acc0.w += v.w;
        }
    }
    float4 acc = make_float4(acc0.x + acc1.x, acc0.y + acc1.y,
                             acc0.z + acc1.z, acc0.w + acc1.w);
    float inv = 1.f / fmaxf((float)c, 1.f);
    acc.x *= inv; acc.y *= inv; acc.z *= inv; acc.w *= inv;
    uint32_t h01, h23, l01, l23;
    split2(acc.x, acc.y, h01, l01);
    split2(acc.z, acc.w, h23, l23);
    *(uint2*)&outH[w * 128 + lane * 4] = make_uint2(h01, h23);
    *(uint2*)&outL[w * 128 + lane * 4] = make_uint2(l01, l23);
}

// ---------------- staging primitives (templated on per-thread iter count) ----------------
template <int NIT> struct StageRegsT { uint4 rH[NIT], rL[NIT]; };

template <int NIT>
__device__ __forceinline__ void stage_load_planes(StageRegsT<NIT>& s, const uint16_t* pH,
                                                  const uint16_t* pL, int row0, int cb,
                                                  int t, int stride) {
    #pragma unroll
    for (int i = 0; i < NIT; i++) {
        int v = t + i * stride, row = v >> 3, f = v & 7, gr = row0 + row;
        if (gr < NN) {
            s.rH[i] = *(const uint4*)(pH + gr * 128 + cb + f * 8);
            s.rL[i] = *(const uint4*)(pL + gr * 128 + cb + f * 8);
        } else {
            s.rH[i] = make_uint4(0, 0, 0, 0);
            s.rL[i] = make_uint4(0, 0, 0, 0);
        }
    }
}
template <int NIT>
__device__ __forceinline__ void stage_load_f32(StageRegsT<NIT>& s, const float* xf,
                                               int row0, int cb16, int t, int stride) {
    const float4* x4 = (const float4*)xf;
    #pragma unroll
    for (int i = 0; i < NIT; i++) {
        int v = t + i * stride, row = v >> 3, f = v & 7, gr = row0 + row;
        float4 a = make_float4(0.f, 0.f, 0.f, 0.f);
        float4 b = make_float4(0.f, 0.f, 0.f, 0.f);
        if (gr < NN) {
            a = x4[gr * 32 + cb16 + f * 2];
            b = x4[gr * 32 + cb16 + f * 2 + 1];
        }
        uint32_t h01, h23, h45, h67, l01, l23, l45, l67;
        split2(a.x, a.y, h01, l01);
        split2(a.z, a.w, h23, l23);
        split2(b.x, b.y, h45, l45);
        split2(b.z, b.w, h67, l67);
        s.rH[i] = make_uint4(h01, h23, h45, h67);
        s.rL[i] = make_uint4(l01, l23, l45, l67);
    }
}
template <int NIT>
__device__ __forceinline__ void stage_store(const StageRegsT<NIT>& s, char* AH, char* AL,
                                            int t, int stride) {
    #pragma unroll
    for (int i = 0; i < NIT; i++) {
        int v = t + i * stride, row = v >> 3, f = v & 7;
        *(uint4*)(AH + row * 144 + f * 16) = s.rH[i];
        *(uint4*)(AL + row * 144 + f * 16) = s.rL[i];
    }
}

// ================= persistent pipelined layer GEMM: 512 threads, 16 warps =========
// warp tile 32x32; smem: bias 512 | A dbuf 2x36864 | W 147456 => 221696 B
#define L_SM_A    512
#define L_SM_W    (512 + 4 * 18432)
#define L_SMEM_BYTES (L_SM_W + 147456)

__global__ __launch_bounds__(512, 1) void k_layer_tc(
    const uint16_t* __restrict__ aggH, const uint16_t* __restrict__ aggL,
    const uint16_t* xH, const uint16_t* xL,
    const float* __restrict__ xf32,
    const uint16_t* __restrict__ wprep, const float* __restrict__ bias,
    float* __restrict__ hout, uint16_t* outH, uint16_t* outL, int write_f32) {
    extern __shared__ __align__(16) char smem[];
    int t = threadIdx.x;
    int wid = t >> 5, lane = t & 31;
    int g = lane >> 2, q = lane & 3;
    int wm = wid & 3, wn = wid >> 2;    // rows wm*32.., cols wn*32..

    {
        const uint4* src = (const uint4*)wprep;
        uint4* dst = (uint4*)(smem + L_SM_W);
        #pragma unroll
        for (int it = 0; it < 18; it++) dst[t + it * 512] = src[t + it * 512];
    }
    if (t < 128) ((float*)smem)[t] = bias[t];

    uint32_t smemS = (uint32_t)__cvta_generic_to_shared(smem);
    int tile4 = lane >> 3, r8 = lane & 7;
    uint32_t laneA = (uint32_t)((((tile4 & 1) * 8 + r8) * 144) + (tile4 >> 1) * 16);
    uint32_t laneB = (uint32_t)((((tile4 >> 1) * 8 + r8) * 144) + (tile4 & 1) * 16);
    uint32_t aRow0 = (uint32_t)((wm * 32) * 144);
    uint32_t bRow0 = (uint32_t)((wn * 32) * 144);

    auto load_chunk = [&](StageRegsT<2>& s, int cc, int r0) {
        if (cc < 2)
            stage_load_planes<2>(s, aggH, aggL, r0, cc * 64, t, 512);
        else if (xf32)
            stage_load_f32<2>(s, xf32, r0, (cc - 2) * 16, t, 512);
        else
            stage_load_planes<2>(s, xH, xL, r0, (cc - 2) * 64, t, 512);
    };

    StageRegsT<2> sr;
    load_chunk(sr, 0, blockIdx.x * 128);
    stage_store<2>(sr, smem + L_SM_A, smem + L_SM_A + 18432, t, 512);
    __syncthreads();

    for (int tile = blockIdx.x; tile < NTILES; tile += GRID_P) {
        int row0 = tile * 128;

        float acc[2][4][4];
        #pragma unroll
        for (int mi = 0; mi < 2; mi++)
            #pragma unroll
            for (int ni = 0; ni < 4; ni++)
                #pragma unroll
                for (int r = 0; r < 4; r++) acc[mi][ni][r] = 0.f;

        #pragma unroll
        for (int c = 0; c < 4; c++) {
            if (c < 3) load_chunk(sr, c + 1, row0);
            else       load_chunk(sr, 0, row0 + GRID_P * 128);

            uint32_t AhS = smemS + L_SM_A + (c & 1) * 36864 + aRow0 + laneA;
            uint32_t AlS = AhS + 18432;
            uint32_t BhS = smemS + L_SM_W + c * 18432 + bRow0 + laneB;
            uint32_t BlS = BhS + 4 * 18432;

            #pragma unroll
            for (int ks = 0; ks < 4; ks++) {
                uint32_t ksb = ks * 32;
                uint32_t ah[2][4], al[2][4];
                ldsm4(ah[0], AhS + ksb);
                ldsm4(ah[1], AhS + 16 * 144 + ksb);
                ldsm4(al[0], AlS + ksb);
                ldsm4(al[1], AlS + 16 * 144 + ksb);
                #pragma unroll
                for (int nj = 0; nj < 2; nj++) {
                    uint32_t bh[4], bl[4];
                    ldsm4(bh, BhS + nj * (16 * 144) + ksb);
                    ldsm4(bl, BlS + nj * (16 * 144) + ksb);
                    #pragma unroll
                    for (int mi = 0; mi < 2; mi++) {
                        mma_bf16(acc[mi][2 * nj],     ah[mi], bh);
                        mma_bf16(acc[mi][2 * nj],     al[mi], bh);
                        mma_bf16(acc[mi][2 * nj],     ah[mi], bl);
                        mma_bf16(acc[mi][2 * nj + 1], ah[mi], bh + 2);
                        mma_bf16(acc[mi][2 * nj + 1], al[mi], bh + 2);
                        mma_bf16(acc[mi][2 * nj + 1], ah[mi], bl + 2);
                    }
                }
            }

            {
                char* AHn = smem + L_SM_A + ((c + 1) & 1) * 36864;
                stage_store<2>(sr, AHn, AHn + 18432, t, 512);
                __syncthreads();
            }
        }

        const float* bsm = (const float*)smem;
        #pragma unroll
        for (int mi = 0; mi < 2; mi++) {
            #pragma unroll
            for (int ni = 0; ni < 4; ni++) {
                int col = wn * 32 + ni * 8 + 2 * q;
                float b0 = bsm[col], b1 = bsm[col + 1];
                int rlo = row0 + wm * 32 + mi * 16 + g;
                int rhi = rlo + 8;
                if (rlo < NN) {
                    float o0 = mish2(acc[mi][ni][0] + b0);
                    float o1 = mish2(acc[mi][ni][1] + b1);
                    if (write_f32) *(float2*)&hout[rlo * 128 + col] = make_float2(o0, o1);
                    uint32_t hh, ll;
                    split2(o0, o1, hh, ll);
                    *(uint32_t*)&outH[rlo * 128 + col] = hh;
                    *(uint32_t*)&outL[rlo * 128 + col] = ll;
                }
                if (rhi < NN) {
                    float o0 = mish2(acc[mi][ni][2] + b0);
                    float o1 = mish2(acc[mi][ni][3] + b1);
                    if (write_f32) *(float2*)&hout[rhi * 128 + col] = make_float2(o0, o1);
                    uint32_t hh, ll;
                    split2(o0, o1, hh, ll);
                    *(uint32_t*)&outH[rhi * 128 + col] = hh;
                    *(uint32_t*)&outL[rhi * 128 + col] = ll;
                }
            }
        }
    }
}

// ================= persistent pipelined head (256 threads): out = h @ Wh^T + b =========
#define H_SM_A    512
#define H_SM_W    (512 + 4 * 18432)
#define H_SMEM_BYTES (H_SM_W + 36864)

__global__ __launch_bounds__(256, 1) void k_head_tc(
    const uint16_t* __restrict__ xH, const uint16_t* __restrict__ xL,
    const uint16_t* __restrict__ wprep, const float* __restrict__ bias,
    float* __restrict__ outp) {
    extern __shared__ __align__(16) char smem[];
    int t = threadIdx.x;
    int wid = t >> 5, lane = t & 31;
    int g = lane >> 2, q = lane & 3;

    {
        const uint4* src = (const uint4*)wprep;
        uint4* dst = (uint4*)(smem + H_SM_W);
        #pragma unroll
        for (int it = 0; it < 9; it++) dst[t + it * 256] = src[t + it * 256];
    }
    if (t < 64) ((float*)smem)[t] = bias[t];

    uint32_t smemS = (uint32_t)__cvta_generic_to_shared(smem);
    int tile4 = lane >> 3, r8 = lane & 7;
    uint32_t laneA = (uint32_t)((((tile4 & 1) * 8 + r8) * 144) + (tile4 >> 1) * 16);
    uint32_t laneB = (uint32_t)((((tile4 >> 1) * 8 + r8) * 144) + (tile4 & 1) * 16);
    uint32_t aRow0 = (uint32_t)((wid * 16) * 144);

    StageRegsT<4> sr;
    stage_load_planes<4>(sr, xH, xL, blockIdx.x * 128, 0, t, 256);
    stage_store<4>(sr, smem + H_SM_A, smem + H_SM_A + 18432, t, 256);
    __syncthreads();

    for (int tile = blockIdx.x; tile < NTILES; tile += GRID_P) {
        int row0 = tile * 128;

        float acc[8][4];
        #pragma unroll
        for (int ni = 0; ni < 8; ni++)
            #pragma unroll
            for (int r = 0; r < 4; r++) acc[ni][r] = 0.f;

        #pragma unroll
        for (int c = 0; c < 2; c++) {
            if (c < 1) stage_load_planes<4>(sr, xH, xL, row0, 64, t, 256);
            else       stage_load_planes<4>(sr, xH, xL, row0 + GRID_P * 128, 0, t, 256);

            uint32_t AhS = smemS + H_SM_A + (c & 1) * 36864 + aRow0 + laneA;
            uint32_t AlS = AhS + 18432;
            uint32_t BhS = smemS + H_SM_W + c * 9216 + laneB;
            uint32_t BlS = BhS + 2 * 9216;

            #pragma unroll
            for (int ks = 0; ks < 4; ks++) {
                uint32_t ksb = ks * 32;
                uint32_t ah[4], al[4];
                ldsm4(ah, AhS + ksb);
                ldsm4(al, AlS + ksb);
                #pragma unroll
                for (int nip = 0; nip < 4; nip++) {
                    uint32_t bh[4], bl[4];
                    ldsm4(bh, BhS + nip * (16 * 144) + ksb);
                    ldsm4(bl, BlS + nip * (16 * 144) + ksb);
                    mma_bf16(acc[2 * nip],     ah, bh);
                    mma_bf16(acc[2 * nip],     al, bh);
                    mma_bf16(acc[2 * nip],     ah, bl);
                    mma_bf16(acc[2 * nip + 1], ah, bh + 2);
                    mma_bf16(acc[2 * nip + 1], al, bh + 2);
                    mma_bf16(acc[2 * nip + 1], ah, bl + 2);
                }
            }

            {
                char* AHn = smem + H_SM_A + ((c + 1) & 1) * 36864;
                stage_store<4>(sr, AHn, AHn + 18432, t, 256);
                __syncthreads();
            }
        }

        const float* bsm = (const float*)smem;
        #pragma unroll
        for (int ni = 0; ni < 8; ni++) {
            int col = ni * 8 + 2 * q;
            float b0 = bsm[col], b1 = bsm[col + 1];
            int rlo = row0 + wid * 16 + g;
            int rhi = rlo + 8;
            if (rlo < NN)
                *(float2*)&outp[rlo * 64 + col] =
                    make_float2(acc[ni][0] + b0, acc[ni][1] + b1);
            if (rhi < NN)
                *(float2*)&outp[rhi * 64 + col] =
                    make_float2(acc[ni][2] + b0, acc[ni][3] + b1);
        }
    }

    // tail: re-zero counters for the next graph replay (this kernel is last)
    int gtid = blockIdx.x * 256 + t;
    for (int i = gtid; i < NN; i += GRID_P * 256) { g_cnt[i] = 0; g_cur[i] = 0; }
    if (gtid < NB_SCAN) g_pkt[gtid] = 0ull;
}

// ---------------- launch ----------------
extern "C" void kernel_launch(void* const* d_in, const int* in_sizes, int n_in,
                              void* d_out, int out_size) {
    (void)in_sizes; (void)n_in; (void)out_size;
    const float* x      = (const float*)d_in[0];
    const int*   edge   = (const int*)d_in[1];     // int32 on device (JAX x64 off)
    const float* W_l0   = (const float*)d_in[2];
    const float* b_l0   = (const float*)d_in[3];
    const float* W_r0   = (const float*)d_in[4];
    const float* W_l1   = (const float*)d_in[5];
    const float* b_l1   = (const float*)d_in[6];
    const float* W_r1   = (const float*)d_in[7];
    const float* W_head = (const float*)d_in[8];
    const float* b_head = (const float*)d_in[9];
    float* out = (float*)d_out;

    cudaFuncSetAttribute(k_layer_tc, cudaFuncAttributeMaxDynamicSharedMemorySize,
                         L_SMEM_BYTES);
    cudaFuncSetAttribute(k_head_tc, cudaFuncAttributeMaxDynamicSharedMemorySize,
                         H_SMEM_BYTES);

    float *h_p;
    uint16_t *aggH_p, *aggL_p, *xH_p, *xL_p, *wb0_p, *wb1_p, *wbh_p;
    cudaGetSymbolAddress((void**)&h_p,    g_h);
    cudaGetSymbolAddress((void**)&aggH_p, g_aggH);
    cudaGetSymbolAddress((void**)&aggL_p, g_aggL);
    cudaGetSymbolAddress((void**)&xH_p,   g_xH);
    cudaGetSymbolAddress((void**)&xL_p,   g_xL);
    cudaGetSymbolAddress((void**)&wb0_p,  g_WB0);
    cudaGetSymbolAddress((void**)&wb1_p,  g_WB1);
    cudaGetSymbolAddress((void**)&wbh_p,  g_WBh);

    int agg_grid = (NN * 32 + 255) / 256;

    // counters zero at load; re-zeroed by k_head_tc tail each call.
    // launch index 3 (the ncu-profiled slot) is k_aggregate.
    k_hist_prep<<<HIST_BLOCKS + 72, 256>>>(edge, W_l0, W_r0, W_l1, W_r1, W_head); // 0
    k_scan<<<NB_SCAN, 512>>>();                                                   // 1
    k_scatter<<<EE / 256, 256>>>(edge);                                           // 2
    k_aggregate<<<agg_grid, 256>>>(x, aggH_p, aggL_p);                            // 3 <- profiled
    k_layer_tc<<<GRID_P, 512, L_SMEM_BYTES>>>(aggH_p, aggL_p, nullptr, nullptr, x,
                                              wb0_p, b_l0, h_p, xH_p, xL_p, 1);   // 4
    k_aggregate<<<agg_grid, 256>>>(h_p, aggH_p, aggL_p);                          // 5
    k_layer_tc<<<GRID_P, 512, L_SMEM_BYTES>>>(aggH_p, aggL_p, xH_p, xL_p, nullptr,
                                              wb1_p, b_l1, h_p, xH_p, xL_p, 0);   // 6
    k_head_tc<<<GRID_P, 256, H_SMEM_BYTES>>>(xH_p, xL_p, wbh_p, b_head, out);     // 7
}

// round 14
// speedup vs baseline: 2.2474x; 1.0572x over previous
#include <cuda_runtime.h>
#include <cuda_bf16.h>
#include <cstdint>

#define NN 100000
#define EE 1600000
#define DH 128
#define NTILES ((NN + 127) / 128)   // 782
#define GRID_P 148
#define NB_SCAN ((NN + 511) / 512)  // 196
#define HIST_BLOCKS (EE / 256)      // 6250

// ---------------- device scratch ----------------
__device__ __align__(16) uint16_t g_aggH[NN * DH];
__device__ __align__(16) uint16_t g_aggL[NN * DH];
__device__ __align__(16) uint16_t g_xH[NN * DH];
__device__ __align__(16) uint16_t g_xL[NN * DH];
__device__ float g_h[NN * DH];
__device__ int   g_cnt[NN];          // zero-init at load; re-zeroed by k_head_tc tail
__device__ int   g_cur[NN];
__device__ int   g_off[NN];
__device__ int   g_srcsorted[EE];
__device__ unsigned long long g_pkt[NB_SCAN];
__device__ __align__(16) uint16_t g_WB0[2 * 4 * 128 * 72];
__device__ __align__(16) uint16_t g_WB1[2 * 4 * 128 * 72];
__device__ __align__(16) uint16_t g_WBh[2 * 2 * 64 * 72];

// ---------------- helpers ----------------
__device__ __forceinline__ void split2(float a, float b, uint32_t& h, uint32_t& l) {
    __nv_bfloat16 ha = __float2bfloat16_rn(a);
    __nv_bfloat16 hb = __float2bfloat16_rn(b);
    __nv_bfloat16 la = __float2bfloat16_rn(a - __bfloat162float(ha));
    __nv_bfloat16 lb = __float2bfloat16_rn(b - __bfloat162float(hb));
    h = (uint32_t)__bfloat16_as_ushort(ha) | ((uint32_t)__bfloat16_as_ushort(hb) << 16);
    l = (uint32_t)__bfloat16_as_ushort(la) | ((uint32_t)__bfloat16_as_ushort(lb) << 16);
}
__device__ __forceinline__ float mish2(float v) {
    float t = __expf(fminf(v, 30.f));
    float r = t * t + 2.f * t;
    return v * (r / (r + 2.f));
}
__device__ __forceinline__ void mma_bf16(float* c, const uint32_t* a, const uint32_t* b) {
    asm volatile(
        "mma.sync.aligned.m16n8k16.row.col.f32.bf16.bf16.f32 "
        "{%0,%1,%2,%3}, {%4,%5,%6,%7}, {%8,%9}, {%0,%1,%2,%3};"
        : "+f"(c[0]), "+f"(c[1]), "+f"(c[2]), "+f"(c[3])
        : "r"(a[0]), "r"(a[1]), "r"(a[2]), "r"(a[3]), "r"(b[0]), "r"(b[1]));
}
__device__ __forceinline__ void ldsm4(uint32_t* r, uint32_t a) {
    asm volatile("ldmatrix.sync.aligned.m8n8.x4.shared.b16 {%0,%1,%2,%3}, [%4];"
        : "=r"(r[0]), "=r"(r[1]), "=r"(r[2]), "=r"(r[3]) : "r"(a));
}

// ---------------- fused hist + weight prep ----------------
__device__ __forceinline__ void prep_layer_elem(const float* Wl, const float* Wr,
                                                uint16_t* outw, int idx) {
    int n = idx >> 6;
    int kg = (idx & 63) * 4;
    const float* Ws = (kg < 128) ? Wl : Wr;
    float4 v = *(const float4*)&Ws[n * 128 + (kg & 127)];
    uint32_t h01, h23, l01, l23;
    split2(v.x, v.y, h01, l01);
    split2(v.z, v.w, h23, l23);
    int c = kg >> 6, kk = kg & 63;
    *(uint2*)&outw[((0 * 4 + c) * 128 + n) * 72 + kk] = make_uint2(h01, h23);
    *(uint2*)&outw[((4 + c) * 128 + n) * 72 + kk]     = make_uint2(l01, l23);
}
__global__ void k_hist_prep(const int* __restrict__ edge,
                            const float* __restrict__ Wl0, const float* __restrict__ Wr0,
                            const float* __restrict__ Wl1, const float* __restrict__ Wr1,
                            const float* __restrict__ Wh) {
    int b = blockIdx.x;
    int t = threadIdx.x;
    if (b < HIST_BLOCKS) {
        int e = b * 256 + t;
        atomicAdd(&g_cnt[edge[EE + e]], 1);
    } else {
        int pb = b - HIST_BLOCKS;    // 0..71
        if (pb < 32) {
            prep_layer_elem(Wl0, Wr0, g_WB0, pb * 256 + t);
        } else if (pb < 64) {
            prep_layer_elem(Wl1, Wr1, g_WB1, (pb - 32) * 256 + t);
        } else {
            int idx = (pb - 64) * 256 + t;
            int n = idx >> 5;
            int kg = (idx & 31) * 4;
            float4 v = *(const float4*)&Wh[n * 128 + kg];
            uint32_t h01, h23, l01, l23;
            split2(v.x, v.y, h01, l01);
            split2(v.z, v.w, h23, l23);
            int c = kg >> 6, kk = kg & 63;
            *(uint2*)&g_WBh[((0 * 2 + c) * 64 + n) * 72 + kk] = make_uint2(h01, h23);
            *(uint2*)&g_WBh[((2 + c) * 64 + n) * 72 + kk]     = make_uint2(l01, l23);
        }
    }
}
// single-pass decoupled-lookback exclusive scan of g_cnt -> g_off
__global__ void k_scan() {
    __shared__ int s[512];
    __shared__ int s_prefix;
    int t = threadIdx.x, b = blockIdx.x;
    int i = b * 512 + t;
    int v = (i < NN) ? g_cnt[i] : 0;
    s[t] = v;
    __syncthreads();
    #pragma unroll
    for (int off = 1; off < 512; off <<= 1) {
        int add = (t >= off) ? s[t - off] : 0;
        __syncthreads();
        s[t] += add;
        __syncthreads();
    }
    int total = s[511];
    if (t == 0) {
        atomicExch(&g_pkt[b], (1ull << 62) | (unsigned long long)total);
        long long prefix = 0;
        for (int j = b - 1; j >= 0; j--) {
            unsigned long long p;
            do { p = atomicAdd(&g_pkt[j], 0ull); } while ((p >> 62) == 0ull);
            prefix += (long long)(p & 0x3FFFFFFFFFFFFFFFull);
            if ((p >> 62) == 2ull) break;
        }
        atomicExch(&g_pkt[b], (2ull << 62) | (unsigned long long)(prefix + total));
        s_prefix = (int)prefix;
    }
    __syncthreads();
    if (i < NN) g_off[i] = s[t] - v + s_prefix;
}
__global__ void k_scatter(const int* __restrict__ edge) {
    int e = blockIdx.x * blockDim.x + threadIdx.x;
    if (e < EE) {
        int src = edge[e];
        int dst = edge[EE + e];
        int pos = g_off[dst] + atomicAdd(&g_cur[dst], 1);
        g_srcsorted[pos] = src;
    }
}

// ---------------- aggregation: R10 shape (occ-friendly) + dual accumulators ----------
__global__ __launch_bounds__(256) void k_aggregate(const float* __restrict__ feat,
                                                   uint16_t* __restrict__ outH,
                                                   uint16_t* __restrict__ outL) {
    int w = (blockIdx.x * blockDim.x + threadIdx.x) >> 5;
    if (w >= NN) return;
    int lane = threadIdx.x & 31;
    int start = g_off[w];
    int c = g_cnt[w];
    const float4* f4 = (const float4*)feat;
    float4 acc0 = make_float4(0.f, 0.f, 0.f, 0.f);
    float4 acc1 = make_float4(0.f, 0.f, 0.f, 0.f);
    for (int base = 0; base < c; base += 32) {
        int idx = (base + lane < c) ? g_srcsorted[start + base + lane] : 0;
        int m = min(32, c - base);
        int j = 0;
        for (; j + 4 <= m; j += 4) {
            int s0 = __shfl_sync(0xffffffffu, idx, j + 0);
            int s1 = __shfl_sync(0xffffffffu, idx, j + 1);
            int s2 = __shfl_sync(0xffffffffu, idx, j + 2);
            int s3 = __shfl_sync(0xffffffffu, idx, j + 3);
            float4 v0 = __ldg(&f4[s0 * 32 + lane]);
            float4 v1 = __ldg(&f4[s1 * 32 + lane]);
            float4 v2 = __ldg(&f4[s2 * 32 + lane]);
            float4 v3 = __ldg(&f4[s3 * 32 + lane]);
            acc0.x += v0.x; acc0.y += v0.y; acc0.z += v0.z; acc0.w += v0.w;
            acc1.x += v1.x; acc1.y += v1.y; acc1.z += v1.z; acc1.w += v1.w;
            acc0.x += v2.x; acc0.y += v2.y; acc0.z += v2.z; acc0.w += v2.w;
            acc1.x += v3.x; acc1.y += v3.y; acc1.z += v3.z; acc1.w += v3.w;
        }
        for (; j < m; j++) {
            int s = __shfl_sync(0xffffffffu, idx, j);
            float4 v = __ldg(&f4[s * 32 + lane]);
            acc0.x += v.x; acc0.y += v.y; acc0.z += v.z; acc0.w += v.w;
        }
    }
    float4 acc = make_float4(acc0.x + acc1.x, acc0.y + acc1.y,
                             acc0.z + acc1.z, acc0.w + acc1.w);
    float inv = 1.f / fmaxf((float)c, 1.f);
    acc.x *= inv; acc.y *= inv; acc.z *= inv; acc.w *= inv;
    uint32_t h01, h23, l01, l23;
    split2(acc.x, acc.y, h01, l01);
    split2(acc.z, acc.w, h23, l23);
    *(uint2*)&outH[w * 128 + lane * 4] = make_uint2(h01, h23);
    *(uint2*)&outL[w * 128 + lane * 4] = make_uint2(l01, l23);
}

// ---------------- staging primitives (templated on per-thread iter count) ----------------
template <int NIT> struct StageRegsT { uint4 rH[NIT], rL[NIT]; };

template <int NIT>
__device__ __forceinline__ void stage_load_planes(StageRegsT<NIT>& s, const uint16_t* pH,
                                                  const uint16_t* pL, int row0, int cb,
                                                  int t, int stride) {
    #pragma unroll
    for (int i = 0; i < NIT; i++) {
        int v = t + i * stride, row = v >> 3, f = v & 7, gr = row0 + row;
        if (gr < NN) {
            s.rH[i] = *(const uint4*)(pH + gr * 128 + cb + f * 8);
            s.rL[i] = *(const uint4*)(pL + gr * 128 + cb + f * 8);
        } else {
            s.rH[i] = make_uint4(0, 0, 0, 0);
            s.rL[i] = make_uint4(0, 0, 0, 0);
        }
    }
}
template <int NIT>
__device__ __forceinline__ void stage_load_f32(StageRegsT<NIT>& s, const float* xf,
                                               int row0, int cb16, int t, int stride) {
    const float4* x4 = (const float4*)xf;
    #pragma unroll
    for (int i = 0; i < NIT; i++) {
        int v = t + i * stride, row = v >> 3, f = v & 7, gr = row0 + row;
        float4 a = make_float4(0.f, 0.f, 0.f, 0.f);
        float4 b = make_float4(0.f, 0.f, 0.f, 0.f);
        if (gr < NN) {
            a = x4[gr * 32 + cb16 + f * 2];
            b = x4[gr * 32 + cb16 + f * 2 + 1];
        }
        uint32_t h01, h23, h45, h67, l01, l23, l45, l67;
        split2(a.x, a.y, h01, l01);
        split2(a.z, a.w, h23, l23);
        split2(b.x, b.y, h45, l45);
        split2(b.z, b.w, h67, l67);
        s.rH[i] = make_uint4(h01, h23, h45, h67);
        s.rL[i] = make_uint4(l01, l23, l45, l67);
    }
}
template <int NIT>
__device__ __forceinline__ void stage_store(const StageRegsT<NIT>& s, char* AH, char* AL,
                                            int t, int stride) {
    #pragma unroll
    for (int i = 0; i < NIT; i++) {
        int v = t + i * stride, row = v >> 3, f = v & 7;
        *(uint4*)(AH + row * 144 + f * 16) = s.rH[i];
        *(uint4*)(AL + row * 144 + f * 16) = s.rL[i];
    }
}

// ================= persistent pipelined layer GEMM: 512 threads, 16 warps =========
// warp tile 32x32; smem: bias 512 | A dbuf 2x36864 | W 147456 => 221696 B
#define L_SM_A    512
#define L_SM_W    (512 + 4 * 18432)
#define L_SMEM_BYTES (L_SM_W + 147456)

__global__ __launch_bounds__(512, 1) void k_layer_tc(
    const uint16_t* __restrict__ aggH, const uint16_t* __restrict__ aggL,
    const uint16_t* xH, const uint16_t* xL,
    const float* __restrict__ xf32,
    const uint16_t* __restrict__ wprep, const float* __restrict__ bias,
    float* __restrict__ hout, uint16_t* outH, uint16_t* outL, int write_f32) {
    extern __shared__ __align__(16) char smem[];
    int t = threadIdx.x;
    int wid = t >> 5, lane = t & 31;
    int g = lane >> 2, q = lane & 3;
    int wm = wid & 3, wn = wid >> 2;    // rows wm*32.., cols wn*32..

    {
        const uint4* src = (const uint4*)wprep;
        uint4* dst = (uint4*)(smem + L_SM_W);
        #pragma unroll
        for (int it = 0; it < 18; it++) dst[t + it * 512] = src[t + it * 512];
    }
    if (t < 128) ((float*)smem)[t] = bias[t];

    uint32_t smemS = (uint32_t)__cvta_generic_to_shared(smem);
    int tile4 = lane >> 3, r8 = lane & 7;
    uint32_t laneA = (uint32_t)((((tile4 & 1) * 8 + r8) * 144) + (tile4 >> 1) * 16);
    uint32_t laneB = (uint32_t)((((tile4 >> 1) * 8 + r8) * 144) + (tile4 & 1) * 16);
    uint32_t aRow0 = (uint32_t)((wm * 32) * 144);
    uint32_t bRow0 = (uint32_t)((wn * 32) * 144);

    auto load_chunk = [&](StageRegsT<2>& s, int cc, int r0) {
        if (cc < 2)
            stage_load_planes<2>(s, aggH, aggL, r0, cc * 64, t, 512);
        else if (xf32)
            stage_load_f32<2>(s, xf32, r0, (cc - 2) * 16, t, 512);
        else
            stage_load_planes<2>(s, xH, xL, r0, (cc - 2) * 64, t, 512);
    };

    StageRegsT<2> sr;
    load_chunk(sr, 0, blockIdx.x * 128);
    stage_store<2>(sr, smem + L_SM_A, smem + L_SM_A + 18432, t, 512);
    __syncthreads();

    for (int tile = blockIdx.x; tile < NTILES; tile += GRID_P) {
        int row0 = tile * 128;

        float acc[2][4][4];
        #pragma unroll
        for (int mi = 0; mi < 2; mi++)
            #pragma unroll
            for (int ni = 0; ni < 4; ni++)
                #pragma unroll
                for (int r = 0; r < 4; r++) acc[mi][ni][r] = 0.f;

        #pragma unroll
        for (int c = 0; c < 4; c++) {
            if (c < 3) load_chunk(sr, c + 1, row0);
            else       load_chunk(sr, 0, row0 + GRID_P * 128);

            uint32_t AhS = smemS + L_SM_A + (c & 1) * 36864 + aRow0 + laneA;
            uint32_t AlS = AhS + 18432;
            uint32_t BhS = smemS + L_SM_W + c * 18432 + bRow0 + laneB;
            uint32_t BlS = BhS + 4 * 18432;

            #pragma unroll
            for (int ks = 0; ks < 4; ks++) {
                uint32_t ksb = ks * 32;
                uint32_t ah[2][4], al[2][4];
                ldsm4(ah[0], AhS + ksb);
                ldsm4(ah[1], AhS + 16 * 144 + ksb);
                ldsm4(al[0], AlS + ksb);
                ldsm4(al[1], AlS + 16 * 144 + ksb);
                #pragma unroll
                for (int nj = 0; nj < 2; nj++) {
                    uint32_t bh[4], bl[4];
                    ldsm4(bh, BhS + nj * (16 * 144) + ksb);
                    ldsm4(bl, BlS + nj * (16 * 144) + ksb);
                    #pragma unroll
                    for (int mi = 0; mi < 2; mi++) {
                        mma_bf16(acc[mi][2 * nj],     ah[mi], bh);
                        mma_bf16(acc[mi][2 * nj],     al[mi], bh);
                        mma_bf16(acc[mi][2 * nj],     ah[mi], bl);
                        mma_bf16(acc[mi][2 * nj + 1], ah[mi], bh + 2);
                        mma_bf16(acc[mi][2 * nj + 1], al[mi], bh + 2);
                        mma_bf16(acc[mi][2 * nj + 1], ah[mi], bl + 2);
                    }
                }
            }

            {
                char* AHn = smem + L_SM_A + ((c + 1) & 1) * 36864;
                stage_store<2>(sr, AHn, AHn + 18432, t, 512);
                __syncthreads();
            }
        }

        const float* bsm = (const float*)smem;
        #pragma unroll
        for (int mi = 0; mi < 2; mi++) {
            #pragma unroll
            for (int ni = 0; ni < 4; ni++) {
                int col = wn * 32 + ni * 8 + 2 * q;
                float b0 = bsm[col], b1 = bsm[col + 1];
                int rlo = row0 + wm * 32 + mi * 16 + g;
                int rhi = rlo + 8;
                if (rlo < NN) {
                    float o0 = mish2(acc[mi][ni][0] + b0);
                    float o1 = mish2(acc[mi][ni][1] + b1);
                    if (write_f32) *(float2*)&hout[rlo * 128 + col] = make_float2(o0, o1);
                    uint32_t hh, ll;
                    split2(o0, o1, hh, ll);
                    *(uint32_t*)&outH[rlo * 128 + col] = hh;
                    *(uint32_t*)&outL[rlo * 128 + col] = ll;
                }
                if (rhi < NN) {
                    float o0 = mish2(acc[mi][ni][2] + b0);
                    float o1 = mish2(acc[mi][ni][3] + b1);
                    if (write_f32) *(float2*)&hout[rhi * 128 + col] = make_float2(o0, o1);
                    uint32_t hh, ll;
                    split2(o0, o1, hh, ll);
                    *(uint32_t*)&outH[rhi * 128 + col] = hh;
                    *(uint32_t*)&outL[rhi * 128 + col] = ll;
                }
            }
        }
    }
}

// ================= persistent pipelined head (256 threads): out = h @ Wh^T + b =========
#define H_SM_A    512
#define H_SM_W    (512 + 4 * 18432)
#define H_SMEM_BYTES (H_SM_W + 36864)

__global__ __launch_bounds__(256, 1) void k_head_tc(
    const uint16_t* __restrict__ xH, const uint16_t* __restrict__ xL,
    const uint16_t* __restrict__ wprep, const float* __restrict__ bias,
    float* __restrict__ outp) {
    extern __shared__ __align__(16) char smem[];
    int t = threadIdx.x;
    int wid = t >> 5, lane = t & 31;
    int g = lane >> 2, q = lane & 3;

    {
        const uint4* src = (const uint4*)wprep;
        uint4* dst = (uint4*)(smem + H_SM_W);
        #pragma unroll
        for (int it = 0; it < 9; it++) dst[t + it * 256] = src[t + it * 256];
    }
    if (t < 64) ((float*)smem)[t] = bias[t];

    uint32_t smemS = (uint32_t)__cvta_generic_to_shared(smem);
    int tile4 = lane >> 3, r8 = lane & 7;
    uint32_t laneA = (uint32_t)((((tile4 & 1) * 8 + r8) * 144) + (tile4 >> 1) * 16);
    uint32_t laneB = (uint32_t)((((tile4 >> 1) * 8 + r8) * 144) + (tile4 & 1) * 16);
    uint32_t aRow0 = (uint32_t)((wid * 16) * 144);

    StageRegsT<4> sr;
    stage_load_planes<4>(sr, xH, xL, blockIdx.x * 128, 0, t, 256);
    stage_store<4>(sr, smem + H_SM_A, smem + H_SM_A + 18432, t, 256);
    __syncthreads();

    for (int tile = blockIdx.x; tile < NTILES; tile += GRID_P) {
        int row0 = tile * 128;

        float acc[8][4];
        #pragma unroll
        for (int ni = 0; ni < 8; ni++)
            #pragma unroll
            for (int r = 0; r < 4; r++) acc[ni][r] = 0.f;

        #pragma unroll
        for (int c = 0; c < 2; c++) {
            if (c < 1) stage_load_planes<4>(sr, xH, xL, row0, 64, t, 256);
            else       stage_load_planes<4>(sr, xH, xL, row0 + GRID_P * 128, 0, t, 256);

            uint32_t AhS = smemS + H_SM_A + (c & 1) * 36864 + aRow0 + laneA;
            uint32_t AlS = AhS + 18432;
            uint32_t BhS = smemS + H_SM_W + c * 9216 + laneB;
            uint32_t BlS = BhS + 2 * 9216;

            #pragma unroll
            for (int ks = 0; ks < 4; ks++) {
                uint32_t ksb = ks * 32;
                uint32_t ah[4], al[4];
                ldsm4(ah, AhS + ksb);
                ldsm4(al, AlS + ksb);
                #pragma unroll
                for (int nip = 0; nip < 4; nip++) {
                    uint32_t bh[4], bl[4];
                    ldsm4(bh, BhS + nip * (16 * 144) + ksb);
                    ldsm4(bl, BlS + nip * (16 * 144) + ksb);
                    mma_bf16(acc[2 * nip],     ah, bh);
                    mma_bf16(acc[2 * nip],     al, bh);
                    mma_bf16(acc[2 * nip],     ah, bl);
                    mma_bf16(acc[2 * nip + 1], ah, bh + 2);
                    mma_bf16(acc[2 * nip + 1], al, bh + 2);
                    mma_bf16(acc[2 * nip + 1], ah, bl + 2);
                }
            }

            {
                char* AHn = smem + H_SM_A + ((c + 1) & 1) * 36864;
                stage_store<4>(sr, AHn, AHn + 18432, t, 256);
                __syncthreads();
            }
        }

        const float* bsm = (const float*)smem;
        #pragma unroll
        for (int ni = 0; ni < 8; ni++) {
            int col = ni * 8 + 2 * q;
            float b0 = bsm[col], b1 = bsm[col + 1];
            int rlo = row0 + wid * 16 + g;
            int rhi = rlo + 8;
            if (rlo < NN)
                *(float2*)&outp[rlo * 64 + col] =
                    make_float2(acc[ni][0] + b0, acc[ni][1] + b1);
            if (rhi < NN)
                *(float2*)&outp[rhi * 64 + col] =
                    make_float2(acc[ni][2] + b0, acc[ni][3] + b1);
        }
    }

    // tail: re-zero counters for the next graph replay (this kernel is last)
    int gtid = blockIdx.x * 256 + t;
    for (int i = gtid; i < NN; i += GRID_P * 256) { g_cnt[i] = 0; g_cur[i] = 0; }
    if (gtid < NB_SCAN) g_pkt[gtid] = 0ull;
}

// ---------------- launch ----------------
extern "C" void kernel_launch(void* const* d_in, const int* in_sizes, int n_in,
                              void* d_out, int out_size) {
    (void)in_sizes; (void)n_in; (void)out_size;
    const float* x      = (const float*)d_in[0];
    const int*   edge   = (const int*)d_in[1];     // int32 on device (JAX x64 off)
    const float* W_l0   = (const float*)d_in[2];
    const float* b_l0   = (const float*)d_in[3];
    const float* W_r0   = (const float*)d_in[4];
    const float* W_l1   = (const float*)d_in[5];
    const float* b_l1   = (const float*)d_in[6];
    const float* W_r1   = (const float*)d_in[7];
    const float* W_head = (const float*)d_in[8];
    const float* b_head = (const float*)d_in[9];
    float* out = (float*)d_out;

    cudaFuncSetAttribute(k_layer_tc, cudaFuncAttributeMaxDynamicSharedMemorySize,
                         L_SMEM_BYTES);
    cudaFuncSetAttribute(k_head_tc, cudaFuncAttributeMaxDynamicSharedMemorySize,
                         H_SMEM_BYTES);

    float *h_p;
    uint16_t *aggH_p, *aggL_p, *xH_p, *xL_p, *wb0_p, *wb1_p, *wbh_p;
    cudaGetSymbolAddress((void**)&h_p,    g_h);
    cudaGetSymbolAddress((void**)&aggH_p, g_aggH);
    cudaGetSymbolAddress((void**)&aggL_p, g_aggL);
    cudaGetSymbolAddress((void**)&xH_p,   g_xH);
    cudaGetSymbolAddress((void**)&xL_p,   g_xL);
    cudaGetSymbolAddress((void**)&wb0_p,  g_WB0);
    cudaGetSymbolAddress((void**)&wb1_p,  g_WB1);
    cudaGetSymbolAddress((void**)&wbh_p,  g_WBh);

    int agg_grid = (NN * 32 + 255) / 256;

    // counters zero at load; re-zeroed by k_head_tc tail each call.
    // launch index 3 (the ncu-profiled slot) is k_aggregate.
    k_hist_prep<<<HIST_BLOCKS + 72, 256>>>(edge, W_l0, W_r0, W_l1, W_r1, W_head); // 0
    k_scan<<<NB_SCAN, 512>>>();                                                   // 1
    k_scatter<<<EE / 256, 256>>>(edge);                                           // 2
    k_aggregate<<<agg_grid, 256>>>(x, aggH_p, aggL_p);                            // 3 <- profiled
    k_layer_tc<<<GRID_P, 512, L_SMEM_BYTES>>>(aggH_p, aggL_p, nullptr, nullptr, x,
                                              wb0_p, b_l0, h_p, xH_p, xL_p, 1);   // 4
    k_aggregate<<<agg_grid, 256>>>(h_p, aggH_p, aggL_p);                          // 5
    k_layer_tc<<<GRID_P, 512, L_SMEM_BYTES>>>(aggH_p, aggL_p, xH_p, xL_p, nullptr,
                                              wb1_p, b_l1, h_p, xH_p, xL_p, 0);   // 6
    k_head_tc<<<GRID_P, 256, H_SMEM_BYTES>>>(xH_p, xL_p, wbh_p, b_head, out);     // 7
}